// round 13
// baseline (speedup 1.0000x reference)
#include <cuda_runtime.h>
#include <cuda_fp16.h>
#include <math.h>
#include <cstdint>

// Problem shape (fixed by the dataset)
#define Bq  4
#define Sq  2048
#define Dq  1024
#define Hq  16
#define HDq 64
#define Mrows (Bq*Sq)          // 8192
#define Kdim 1024

// ---------------------------------------------------------------------------
// Scratch (device globals). fp16 asymmetric 2-product scheme:
//   activations (x, k, v, attn-out) stored SPLIT (hi+lo)
//   weights / q / p stored HI-ONLY (dropped residual ~2^-12 rel)
// ---------------------------------------------------------------------------
__device__ __half g_xh [(size_t)Mrows * Kdim];
__device__ __half g_xl [(size_t)Mrows * Kdim];
__device__ __half g_w1h[(size_t)3 * Dq * Kdim];          // WqkvT hi only
__device__ __half g_w2h[(size_t)Dq * Kdim];              // WoutT hi only
__device__ __half g_ah [(size_t)Mrows * Kdim];           // attn out hi, [b,s,D]
__device__ __half g_al [(size_t)Mrows * Kdim];           // attn out lo

#define QKV_ELEMS ((size_t)Bq*Hq*Sq*HDq)
// Q/K use PERMUTED head-dim layout (pos 2j = rope[j], 2j+1 = rope[32+j]);
// QK^T invariant under common permutation of the contraction axis.
__device__ __half g_qh[QKV_ELEMS];                       // Q hi only
__device__ __half g_kh[QKV_ELEMS];
__device__ __half g_kl[QKV_ELEMS];
__device__ __half g_vh[QKV_ELEMS];
__device__ __half g_vl[QKV_ELEMS];

// ---------------------------------------------------------------------------
// PTX helpers (plain sm_80-era features only; toolchain targets sm_103 w/o 'a')
// ---------------------------------------------------------------------------
__device__ __forceinline__ uint32_t smem_u32(const void* p) {
    uint32_t a;
    asm("{ .reg .u64 t; cvta.to.shared.u64 t, %1; cvt.u32.u64 %0, t; }"
        : "=r"(a) : "l"(p));
    return a;
}
__device__ __forceinline__ void cp_async16(uint32_t s, const void* g) {
    asm volatile("cp.async.cg.shared.global [%0], [%1], 16;" :: "r"(s), "l"(g));
}
__device__ __forceinline__ void cp_commit() {
    asm volatile("cp.async.commit_group;" ::: "memory");
}
template<int N> __device__ __forceinline__ void cp_wait() {
    asm volatile("cp.async.wait_group %0;" :: "n"(N) : "memory");
}
__device__ __forceinline__ void ldmx4(uint32_t addr, uint32_t* r) {
    asm volatile("ldmatrix.sync.aligned.m8n8.x4.shared.b16 {%0,%1,%2,%3}, [%4];"
        : "=r"(r[0]), "=r"(r[1]), "=r"(r[2]), "=r"(r[3]) : "r"(addr));
}
__device__ __forceinline__ void ldmx4t(uint32_t addr, uint32_t* r) {
    asm volatile("ldmatrix.sync.aligned.m8n8.x4.trans.shared.b16 {%0,%1,%2,%3}, [%4];"
        : "=r"(r[0]), "=r"(r[1]), "=r"(r[2]), "=r"(r[3]) : "r"(addr));
}
__device__ __forceinline__ void mma16816(float* d, const uint32_t* a,
                                         uint32_t b0, uint32_t b1) {
    asm volatile(
        "mma.sync.aligned.m16n8k16.row.col.f32.f16.f16.f32 "
        "{%0,%1,%2,%3}, {%4,%5,%6,%7}, {%8,%9}, {%0,%1,%2,%3};"
        : "+f"(d[0]), "+f"(d[1]), "+f"(d[2]), "+f"(d[3])
        : "r"(a[0]), "r"(a[1]), "r"(a[2]), "r"(a[3]), "r"(b0), "r"(b1));
}
__device__ __forceinline__ uint32_t pack_h(float x0, float x1) {
    __half2 h = __floats2half2_rn(x0, x1);
    return *(uint32_t*)&h;
}
// pack two fp32 into fp16x2 hi; residual lo via out-param
__device__ __forceinline__ uint32_t packsplit_h(float x0, float x1, uint32_t& lo) {
    __half h0 = __float2half_rn(x0), h1 = __float2half_rn(x1);
    lo = pack_h(x0 - __half2float(h0), x1 - __half2float(h1));
    return (uint32_t)__half_as_ushort(h0) | ((uint32_t)__half_as_ushort(h1) << 16);
}

// ---------------------------------------------------------------------------
// Split-fp16 conversion: x -> (hi, lo)
// ---------------------------------------------------------------------------
__global__ __launch_bounds__(256) void split_kernel(
    const float* __restrict__ x, __half* __restrict__ hi,
    __half* __restrict__ lo, int n4)
{
    int i = blockIdx.x * blockDim.x + threadIdx.x;
    if (i >= n4) return;
    float4 v = ((const float4*)x)[i];
    uint32_t l01, l23;
    uint32_t h01 = packsplit_h(v.x, v.y, l01);
    uint32_t h23 = packsplit_h(v.z, v.w, l23);
    ((uint2*)hi)[i] = make_uint2(h01, h23);
    ((uint2*)lo)[i] = make_uint2(l01, l23);
}

// ---------------------------------------------------------------------------
// Transpose: W[K,N] fp32 -> T[N,K] fp16 hi only
// ---------------------------------------------------------------------------
__global__ __launch_bounds__(256) void transpose_half_kernel(
    const float* __restrict__ W, __half* __restrict__ Th, int K, int N)
{
    __shared__ float t[32][33];
    int n0 = blockIdx.x * 32, k0 = blockIdx.y * 32;
    int tx = threadIdx.x, ty = threadIdx.y;   // (32, 8)
    #pragma unroll
    for (int i = 0; i < 32; i += 8)
        t[ty + i][tx] = W[(size_t)(k0 + ty + i) * N + n0 + tx];
    __syncthreads();
    #pragma unroll
    for (int i = 0; i < 32; i += 8)
        Th[(size_t)(n0 + ty + i) * K + k0 + tx] = __float2half_rn(t[tx][ty + i]);
}

// ---------------------------------------------------------------------------
// GEMM core (R12, unchanged): C = A @ B^T. A split (hi+lo), B hi-only.
// 128x128 tile, BK=32, 256 thr / 8 warps (64x32 warp tile), 2 CTAs/SM.
// 4 smem stages, one wait+sync per TWO k-tiles.
// ---------------------------------------------------------------------------
#define NKT      (Kdim / 32)       // 32
#define TILE8K   8192              // one 128x32 fp16 tile
#define STAGE_B  (3 * TILE8K)      // 24 KB per stage (Ah, Al, Bh)
#define GEMM_SMEM (4 * STAGE_B)    // 96 KB -> 2 CTAs/SM

#define GEMM_PROLOGUE_AND_MAINLOOP(AhiP, AloP, BhP)                           \
    extern __shared__ char sm[];                                              \
    const uint32_t sbase = smem_u32(sm);                                      \
    const int tid = threadIdx.x, wid = tid >> 5, lane = tid & 31;             \
    const int row0 = blockIdx.y * 128, col0 = blockIdx.x * 128;               \
    const int wm = (wid >> 2) * 64, wn = (wid & 3) * 32;                      \
    const __half* gsrc[3] = {                                                 \
        AhiP + (size_t)row0 * Kdim, AloP + (size_t)row0 * Kdim,               \
        BhP + (size_t)col0 * Kdim };                                          \
    float acc[4][4][4];                                                       \
    _Pragma("unroll")                                                         \
    for (int i = 0; i < 4; i++)                                               \
        _Pragma("unroll")                                                     \
        for (int j = 0; j < 4; j++)                                           \
            _Pragma("unroll")                                                 \
            for (int r = 0; r < 4; r++) acc[i][j][r] = 0.f;                   \
    auto LOAD = [&](int ct, int st) {                                         \
        const int kk = ct * 32;                                               \
        const uint32_t sb = sbase + st * STAGE_B;                             \
        _Pragma("unroll")                                                     \
        for (int it = 0; it < 6; it++) {                                      \
            int i   = tid + it * 256;       /* 1536 chunks */                 \
            int t   = i >> 9;                                                 \
            int rem = i & 511;                                                \
            int row = rem >> 2;                                               \
            int ch  = rem & 3;                                                \
            uint32_t so = sb + t * TILE8K + row * 64                          \
                        + ((uint32_t)(ch ^ ((row >> 1) & 3)) << 4);           \
            cp_async16(so, gsrc[t] + (size_t)row * Kdim + kk + ch * 8);       \
        }                                                                     \
    };                                                                        \
    auto COMPUTE = [&](int st) {                                              \
        const uint32_t Ah = sbase + st * STAGE_B;                             \
        const uint32_t Al = Ah + TILE8K, Bh = Ah + 2 * TILE8K;                \
        const int g = lane >> 3, lr = lane & 7;                               \
        _Pragma("unroll")                                                     \
        for (int s = 0; s < 2; s++) {                                         \
            uint32_t af[4][4], alf[4][4], bf[2][4];                           \
            _Pragma("unroll")                                                 \
            for (int i = 0; i < 4; i++) {                                     \
                int row = wm + 16 * i + (g & 1) * 8 + lr;                     \
                int ch  = 2 * s + (g >> 1);                                   \
                uint32_t off = (uint32_t)(row * 64                            \
                              + ((ch ^ ((row >> 1) & 3)) << 4));              \
                ldmx4(Ah + off, af[i]);                                       \
                ldmx4(Al + off, alf[i]);                                      \
            }                                                                 \
            _Pragma("unroll")                                                 \
            for (int h = 0; h < 2; h++) {                                     \
                int row = wn + 16 * h + (g >> 1) * 8 + lr;                    \
                int ch  = 2 * s + (g & 1);                                    \
                uint32_t off = (uint32_t)(row * 64                            \
                              + ((ch ^ ((row >> 1) & 3)) << 4));              \
                ldmx4(Bh + off, bf[h]);                                       \
            }                                                                 \
            _Pragma("unroll")                                                 \
            for (int i = 0; i < 4; i++)                                       \
                _Pragma("unroll")                                             \
                for (int j = 0; j < 4; j++) {                                 \
                    const int h = j >> 1, q = j & 1;                          \
                    mma16816(acc[i][j], af[i],  bf[h][2*q], bf[h][2*q+1]);    \
                    mma16816(acc[i][j], alf[i], bf[h][2*q], bf[h][2*q+1]);    \
                }                                                             \
        }                                                                     \
    };                                                                        \
    LOAD(0, 0); cp_commit();                                                  \
    LOAD(1, 1); cp_commit();                                                  \
    _Pragma("unroll 1")                                                       \
    for (int c = 0; c < NKT; c += 2) {                                        \
        cp_wait<0>();                                                         \
        __syncthreads();                                                      \
        if (c + 2 < NKT) { LOAD(c + 2, (c + 2) & 3); cp_commit(); }           \
        if (c + 3 < NKT) { LOAD(c + 3, (c + 3) & 3); cp_commit(); }           \
        COMPUTE(c & 3);                                                       \
        COMPUTE((c + 1) & 3);                                                 \
    }

__global__ __launch_bounds__(256, 2) void gemm_mma(
    const __half* __restrict__ Ahi, const __half* __restrict__ Alo,
    const __half* __restrict__ Bh2, float* __restrict__ C, int N)
{
    GEMM_PROLOGUE_AND_MAINLOOP(Ahi, Alo, Bh2)

    #pragma unroll
    for (int i = 0; i < 4; i++) {
        const int r = row0 + wm + 16 * i + (lane >> 2);
        #pragma unroll
        for (int j = 0; j < 4; j++) {
            const int cc = col0 + wn + 8 * j + (lane & 3) * 2;
            *(float2*)(C + (size_t)r * N + cc) =
                make_float2(acc[i][j][0], acc[i][j][1]);
            *(float2*)(C + (size_t)(r + 8) * N + cc) =
                make_float2(acc[i][j][2], acc[i][j][3]);
        }
    }
}

// Fused QKV projection: RoPE on the in-thread (2j,2j+1) pair, head transpose,
// Q pre-scale; Q written hi-only, K/V split. Permuted hd layout for Q/K.
__global__ __launch_bounds__(256, 2) void gemm_qkv_rope(
    const __half* __restrict__ Ahi, const __half* __restrict__ Alo,
    const __half* __restrict__ Bh2,
    const float* __restrict__ cosp, const float* __restrict__ sinp,
    __half* __restrict__ qh,
    __half* __restrict__ kh, __half* __restrict__ kl,
    __half* __restrict__ vh, __half* __restrict__ vl)
{
    GEMM_PROLOGUE_AND_MAINLOOP(Ahi, Alo, Bh2)

    const float SC = 0.125f * 1.4426950408889634f;   // 1/sqrt(64)*log2(e)
    #pragma unroll
    for (int j = 0; j < 4; j++) {
        const int cc   = col0 + wn + 8 * j + (lane & 3) * 2;
        const int type = cc >> 10;           // 0=q 1=k 2=v (warp-uniform)
        const int remc = cc & 1023;
        const int hh   = remc >> 6, hd = remc & 63, jp = hd >> 1;
        #pragma unroll
        for (int i = 0; i < 4; i++) {
            #pragma unroll
            for (int rr2 = 0; rr2 < 2; rr2++) {
                const int r = row0 + wm + 16 * i + (lane >> 2) + rr2 * 8;
                float e0 = acc[i][j][rr2 * 2];
                float e1 = acc[i][j][rr2 * 2 + 1];
                const int bb = r >> 11, ss = r & (Sq - 1);
                const size_t dst = ((size_t)(bb * Hq + hh) * Sq + ss) * HDq + hd;
                if (type != 2) {
                    const float c  = cosp[ss * 32 + jp];
                    const float sn = sinp[ss * 32 + jp];
                    float a  = e0 * c  - e1 * sn;
                    float b2 = e0 * sn + e1 * c;
                    if (type == 0) {
                        *(uint32_t*)(qh + dst) = pack_h(a * SC, b2 * SC);
                        continue;
                    }
                    e0 = a; e1 = b2;
                }
                uint32_t lo, hi = packsplit_h(e0, e1, lo);
                __half* ph = (type == 1) ? kh : vh;
                __half* pl = (type == 1) ? kl : vl;
                *(uint32_t*)(ph + dst) = hi;
                *(uint32_t*)(pl + dst) = lo;
            }
        }
    }
}

// ---------------------------------------------------------------------------
// Tensor-core causal flash attention (fp16 2-product).
// CTA = 128 queries, 256 thr / 8 warps x 16 q. Each KV tile load now serves
// 128 queries (KV traffic halved vs 64q CTA). SMEM: Q 16KB + 3 x KV 32KB =
// 112KB -> still 2 CTAs/SM (16 warps/SM hide softmax phases).
// ---------------------------------------------------------------------------
#define AKT 64
#define AQT 128
#define ATT_SMEM (16384 + 3 * 32768)   // 114688

__device__ __forceinline__ uint32_t sw_off(int row, int ch) {
    return (uint32_t)(row * 128 + ((ch ^ (row & 7)) << 4));
}

__global__ __launch_bounds__(256, 2) void attn_mma(
    const __half* __restrict__ gqh,
    const __half* __restrict__ gkh, const __half* __restrict__ gkl,
    const __half* __restrict__ gvh, const __half* __restrict__ gvl,
    __half* __restrict__ outh, __half* __restrict__ outl)
{
    extern __shared__ char sm[];
    const uint32_t sbase = smem_u32(sm);
    const uint32_t QH = sbase;
    const int tid = threadIdx.x, wid = tid >> 5, lane = tid & 31;
    const int g = lane >> 3, lr = lane & 7;

    const int qb = (gridDim.x - 1) - blockIdx.x;     // heavy tiles first
    const int h  = blockIdx.y, b = blockIdx.z;
    const int q_base = qb * AQT;
    const int ntile = q_base / AKT + 2;              // covers q_base+128 keys

    const size_t hb = (((size_t)(b * Hq + h)) * Sq) * HDq;
    const __half* kvsrc[4] = {gkh + hb, gkl + hb, gvh + hb, gvl + hb};

    // ---- loaders -----------------------------------------------------------
    auto load_q = [&]() {
        #pragma unroll
        for (int it = 0; it < 4; it++) {
            int i = tid + it * 256;              // 1024 chunks (128r x 8ch)
            int row = i >> 3, ch = i & 7;
            cp_async16(sbase + sw_off(row, ch),
                       gqh + hb + (size_t)(q_base + row) * HDq + ch * 8);
        }
    };
    auto load_kv = [&](int t, int bi) {
        const int k0 = t * AKT;
        const uint32_t sb = sbase + 16384 + bi * 32768;
        #pragma unroll
        for (int it = 0; it < 8; it++) {
            int i = tid + it * 256;              // 2048 chunks (4 arr x 64r x 8ch)
            int arr = i >> 9, rem = i & 511;
            int row = rem >> 3, ch = rem & 7;
            cp_async16(sb + arr * 8192 + sw_off(row, ch),
                       kvsrc[arr] + (size_t)(k0 + row) * HDq + ch * 8);
        }
    };

    // ---- prologue ----------------------------------------------------------
    load_q(); load_kv(0, 0); cp_commit();        // group 0 (Q + KV tile 0)
    load_kv(1, 1); cp_commit();                  // group 1 (KV tile 1)
    cp_wait<1>();                                // group 0 done
    __syncthreads();

    // Q fragments (persist in registers): 4 k16-steps, hi only
    uint32_t qfh[4][4];
    #pragma unroll
    for (int s4 = 0; s4 < 4; s4++) {
        int row = wid * 16 + (g & 1) * 8 + lr;
        int ch  = 2 * s4 + (g >> 1);
        ldmx4(QH + sw_off(row, ch), qfh[s4]);
    }

    float m0 = -1e30f, m1 = -1e30f, l0 = 0.f, l1 = 0.f;
    float o[8][4];
    #pragma unroll
    for (int j = 0; j < 8; j++)
        #pragma unroll
        for (int e = 0; e < 4; e++) o[j][e] = 0.f;

    const int wq = q_base + wid * 16;            // warp's first query row
    const int qg0 = wq + (lane >> 2);            // row for c0,c1 (c2,c3 = +8)

    // ---- main loop (single sync per tile; 3 KV buffers) ---------------------
    for (int t = 0; t < ntile; t++) {
        if (t) { cp_wait<1>(); __syncthreads(); }      // tile-t group complete
        if (t + 2 < ntile) load_kv(t + 2, (t + 2) % 3);
        cp_commit();

        const int k0 = t * AKT;
        const uint32_t BUF = sbase + 16384 + (uint32_t)(t % 3) * 32768;
        const uint32_t KH = BUF, KL = BUF + 8192, VH = BUF + 16384, VL = BUF + 24576;

        if (k0 <= wq + 15) {                     // warp has unmasked rows here
            // ---- scores: S = Q K^T (Qh x (Kh + Kl)) ----
            float s[8][4];
            #pragma unroll
            for (int nt = 0; nt < 8; nt++)
                #pragma unroll
                for (int e = 0; e < 4; e++) s[nt][e] = 0.f;

            #pragma unroll
            for (int kh4 = 0; kh4 < 4; kh4++) {
                #pragma unroll
                for (int s4 = 0; s4 < 4; s4++) {
                    int row = 16 * kh4 + (g >> 1) * 8 + lr;
                    int ch  = 2 * s4 + (g & 1);
                    uint32_t kf[4], lf[4];
                    ldmx4(KH + sw_off(row, ch), kf);
                    ldmx4(KL + sw_off(row, ch), lf);
                    mma16816(s[2*kh4],   qfh[s4], kf[0], kf[1]);
                    mma16816(s[2*kh4],   qfh[s4], lf[0], lf[1]);
                    mma16816(s[2*kh4+1], qfh[s4], kf[2], kf[3]);
                    mma16816(s[2*kh4+1], qfh[s4], lf[2], lf[3]);
                }
            }

            // ---- causal mask (diagonal tiles only) ----
            if (k0 + AKT - 1 > wq) {
                #pragma unroll
                for (int nt = 0; nt < 8; nt++) {
                    int kg = k0 + nt * 8 + (lane & 3) * 2;
                    if (kg     > qg0)     s[nt][0] = -1e30f;
                    if (kg + 1 > qg0)     s[nt][1] = -1e30f;
                    if (kg     > qg0 + 8) s[nt][2] = -1e30f;
                    if (kg + 1 > qg0 + 8) s[nt][3] = -1e30f;
                }
            }

            // ---- online softmax (exp2 domain; scale pre-folded into Q) ----
            float t0 = -1e30f, t1 = -1e30f;
            #pragma unroll
            for (int nt = 0; nt < 8; nt++) {
                t0 = fmaxf(t0, fmaxf(s[nt][0], s[nt][1]));
                t1 = fmaxf(t1, fmaxf(s[nt][2], s[nt][3]));
            }
            t0 = fmaxf(t0, __shfl_xor_sync(0xffffffffu, t0, 1));
            t0 = fmaxf(t0, __shfl_xor_sync(0xffffffffu, t0, 2));
            t1 = fmaxf(t1, __shfl_xor_sync(0xffffffffu, t1, 1));
            t1 = fmaxf(t1, __shfl_xor_sync(0xffffffffu, t1, 2));
            float mn0 = fmaxf(m0, t0), mn1 = fmaxf(m1, t1);
            float c0 = exp2f(m0 - mn0), c1 = exp2f(m1 - mn1);
            m0 = mn0; m1 = mn1;
            l0 *= c0; l1 *= c1;
            #pragma unroll
            for (int j = 0; j < 8; j++) {
                o[j][0] *= c0; o[j][1] *= c0; o[j][2] *= c1; o[j][3] *= c1;
            }
            #pragma unroll
            for (int nt = 0; nt < 8; nt++) {
                s[nt][0] = exp2f(s[nt][0] - mn0);
                s[nt][1] = exp2f(s[nt][1] - mn0);
                s[nt][2] = exp2f(s[nt][2] - mn1);
                s[nt][3] = exp2f(s[nt][3] - mn1);
                l0 += s[nt][0] + s[nt][1];
                l1 += s[nt][2] + s[nt][3];
            }

            // ---- O += P V (Ph x (Vh + Vl)), V via ldmatrix.trans ----
            #pragma unroll
            for (int kp = 0; kp < 4; kp++) {
                uint32_t aph[4];
                aph[0] = pack_h(s[2*kp][0],   s[2*kp][1]);
                aph[1] = pack_h(s[2*kp][2],   s[2*kp][3]);
                aph[2] = pack_h(s[2*kp+1][0], s[2*kp+1][1]);
                aph[3] = pack_h(s[2*kp+1][2], s[2*kp+1][3]);
                #pragma unroll
                for (int j2 = 0; j2 < 4; j2++) {
                    int row = kp * 16 + (g & 1) * 8 + lr;
                    int ch  = 2 * j2 + (g >> 1);
                    uint32_t vf[4], wf[4];
                    ldmx4t(VH + sw_off(row, ch), vf);
                    ldmx4t(VL + sw_off(row, ch), wf);
                    mma16816(o[2*j2],   aph, vf[0], vf[1]);
                    mma16816(o[2*j2],   aph, wf[0], wf[1]);
                    mma16816(o[2*j2+1], aph, vf[2], vf[3]);
                    mma16816(o[2*j2+1], aph, wf[2], wf[3]);
                }
            }
        }
    }

    // ---- normalize + write split-fp16 [b,s,D] (out-proj A operand) ----
    float ls0 = l0 + __shfl_xor_sync(0xffffffffu, l0, 1);
    ls0 += __shfl_xor_sync(0xffffffffu, ls0, 2);
    float ls1 = l1 + __shfl_xor_sync(0xffffffffu, l1, 1);
    ls1 += __shfl_xor_sync(0xffffffffu, ls1, 2);
    const float inv0 = 1.f / ls0, inv1 = 1.f / ls1;

    const size_t base0 = ((size_t)b * Sq + qg0) * Dq + h * HDq;
    const size_t base1 = ((size_t)b * Sq + qg0 + 8) * Dq + h * HDq;
    #pragma unroll
    for (int j = 0; j < 8; j++) {
        int cc = j * 8 + (lane & 3) * 2;
        uint32_t lo0, lo1;
        uint32_t hi0 = packsplit_h(o[j][0] * inv0, o[j][1] * inv0, lo0);
        uint32_t hi1 = packsplit_h(o[j][2] * inv1, o[j][3] * inv1, lo1);
        *(uint32_t*)(outh + base0 + cc) = hi0;
        *(uint32_t*)(outl + base0 + cc) = lo0;
        *(uint32_t*)(outh + base1 + cc) = hi1;
        *(uint32_t*)(outl + base1 + cc) = lo1;
    }
}

// ---------------------------------------------------------------------------
// Launch
// ---------------------------------------------------------------------------
extern "C" void kernel_launch(void* const* d_in, const int* in_sizes, int n_in,
                              void* d_out, int out_size)
{
    const float* x    = (const float*)d_in[0];
    const float* cosp = (const float*)d_in[1];
    const float* sinp = (const float*)d_in[2];
    // d_in[3] = mask: causal -1e9 — handled analytically, never read.
    const float* Wqkv = (const float*)d_in[4];
    const float* Wout = (const float*)d_in[5];
    float* out = (float*)d_out;

    __half *p_xh, *p_xl, *p_w1h, *p_w2h, *p_ah, *p_al;
    __half *p_qh, *p_kh, *p_kl, *p_vh, *p_vl;
    cudaGetSymbolAddress((void**)&p_xh,  g_xh);
    cudaGetSymbolAddress((void**)&p_xl,  g_xl);
    cudaGetSymbolAddress((void**)&p_w1h, g_w1h);
    cudaGetSymbolAddress((void**)&p_w2h, g_w2h);
    cudaGetSymbolAddress((void**)&p_ah,  g_ah);
    cudaGetSymbolAddress((void**)&p_al,  g_al);
    cudaGetSymbolAddress((void**)&p_qh,  g_qh);
    cudaGetSymbolAddress((void**)&p_kh,  g_kh);
    cudaGetSymbolAddress((void**)&p_kl,  g_kl);
    cudaGetSymbolAddress((void**)&p_vh,  g_vh);
    cudaGetSymbolAddress((void**)&p_vl,  g_vl);

    cudaFuncSetAttribute(gemm_mma, cudaFuncAttributeMaxDynamicSharedMemorySize,
                         GEMM_SMEM);
    cudaFuncSetAttribute(gemm_qkv_rope, cudaFuncAttributeMaxDynamicSharedMemorySize,
                         GEMM_SMEM);
    cudaFuncSetAttribute(attn_mma, cudaFuncAttributeMaxDynamicSharedMemorySize,
                         ATT_SMEM);

    // 0) Conversions: x split-fp16; weights transposed fp16 hi-only
    {
        int n4 = Mrows * Kdim / 4;
        split_kernel<<<(n4 + 255) / 256, 256>>>(x, p_xh, p_xl, n4);
        dim3 blk(32, 8);
        transpose_half_kernel<<<dim3(3 * Dq / 32, Kdim / 32), blk>>>(Wqkv, p_w1h, Kdim, 3 * Dq);
        transpose_half_kernel<<<dim3(Dq / 32, Kdim / 32), blk>>>(Wout, p_w2h, Kdim, Dq);
    }
    // 1) QKV projection + fused RoPE/transpose/split (mma.sync fp16)
    {
        dim3 grid(3 * Dq / 128, Mrows / 128);
        gemm_qkv_rope<<<grid, 256, GEMM_SMEM>>>(p_xh, p_xl, p_w1h,
                                                cosp, sinp,
                                                p_qh, p_kh, p_kl, p_vh, p_vl);
    }
    // 2) Tensor-core causal flash attention
    {
        dim3 grid(Sq / AQT, Hq, Bq);
        attn_mma<<<grid, 256, ATT_SMEM>>>(p_qh, p_kh, p_kl, p_vh, p_vl,
                                          p_ah, p_al);
    }
    // 3) Output projection (mma.sync fp16)
    {
        dim3 grid(Dq / 128, Mrows / 128);
        gemm_mma<<<grid, 256, GEMM_SMEM>>>(p_ah, p_al, p_w2h, out, Dq);
    }
}

// round 14
// speedup vs baseline: 1.1287x; 1.1287x over previous
#include <cuda_runtime.h>
#include <cuda_fp16.h>
#include <math.h>
#include <cstdint>

// Problem shape (fixed by the dataset)
#define Bq  4
#define Sq  2048
#define Dq  1024
#define Hq  16
#define HDq 64
#define Mrows (Bq*Sq)          // 8192
#define Kdim 1024

// ---------------------------------------------------------------------------
// Scratch (device globals). fp16 asymmetric 2-product scheme:
//   x, k, attn-out stored SPLIT (hi+lo); weights / q / p / v HI-ONLY.
// ---------------------------------------------------------------------------
__device__ __half g_xh [(size_t)Mrows * Kdim];
__device__ __half g_xl [(size_t)Mrows * Kdim];
__device__ __half g_w1h[(size_t)3 * Dq * Kdim];          // WqkvT hi only
__device__ __half g_w2h[(size_t)Dq * Kdim];              // WoutT hi only
__device__ __half g_ah [(size_t)Mrows * Kdim];           // attn out hi, [b,s,D]
__device__ __half g_al [(size_t)Mrows * Kdim];           // attn out lo

#define QKV_ELEMS ((size_t)Bq*Hq*Sq*HDq)
// Q/K use PERMUTED head-dim layout (pos 2j = rope[j], 2j+1 = rope[32+j]);
// QK^T invariant under common permutation of the contraction axis.
__device__ __half g_qh[QKV_ELEMS];                       // Q hi only
__device__ __half g_kh[QKV_ELEMS];
__device__ __half g_kl[QKV_ELEMS];
__device__ __half g_vh[QKV_ELEMS];                       // V hi only

// ---------------------------------------------------------------------------
// PTX helpers (plain sm_80-era features only; toolchain targets sm_103 w/o 'a')
// ---------------------------------------------------------------------------
__device__ __forceinline__ uint32_t smem_u32(const void* p) {
    uint32_t a;
    asm("{ .reg .u64 t; cvta.to.shared.u64 t, %1; cvt.u32.u64 %0, t; }"
        : "=r"(a) : "l"(p));
    return a;
}
__device__ __forceinline__ void cp_async16(uint32_t s, const void* g) {
    asm volatile("cp.async.cg.shared.global [%0], [%1], 16;" :: "r"(s), "l"(g));
}
__device__ __forceinline__ void cp_commit() {
    asm volatile("cp.async.commit_group;" ::: "memory");
}
template<int N> __device__ __forceinline__ void cp_wait() {
    asm volatile("cp.async.wait_group %0;" :: "n"(N) : "memory");
}
__device__ __forceinline__ void ldmx4(uint32_t addr, uint32_t* r) {
    asm volatile("ldmatrix.sync.aligned.m8n8.x4.shared.b16 {%0,%1,%2,%3}, [%4];"
        : "=r"(r[0]), "=r"(r[1]), "=r"(r[2]), "=r"(r[3]) : "r"(addr));
}
__device__ __forceinline__ void ldmx4t(uint32_t addr, uint32_t* r) {
    asm volatile("ldmatrix.sync.aligned.m8n8.x4.trans.shared.b16 {%0,%1,%2,%3}, [%4];"
        : "=r"(r[0]), "=r"(r[1]), "=r"(r[2]), "=r"(r[3]) : "r"(addr));
}
__device__ __forceinline__ void mma16816(float* d, const uint32_t* a,
                                         uint32_t b0, uint32_t b1) {
    asm volatile(
        "mma.sync.aligned.m16n8k16.row.col.f32.f16.f16.f32 "
        "{%0,%1,%2,%3}, {%4,%5,%6,%7}, {%8,%9}, {%0,%1,%2,%3};"
        : "+f"(d[0]), "+f"(d[1]), "+f"(d[2]), "+f"(d[3])
        : "r"(a[0]), "r"(a[1]), "r"(a[2]), "r"(a[3]), "r"(b0), "r"(b1));
}
__device__ __forceinline__ uint32_t pack_h(float x0, float x1) {
    __half2 h = __floats2half2_rn(x0, x1);
    return *(uint32_t*)&h;
}
// pack two fp32 into fp16x2 hi; residual lo via out-param
__device__ __forceinline__ uint32_t packsplit_h(float x0, float x1, uint32_t& lo) {
    __half h0 = __float2half_rn(x0), h1 = __float2half_rn(x1);
    lo = pack_h(x0 - __half2float(h0), x1 - __half2float(h1));
    return (uint32_t)__half_as_ushort(h0) | ((uint32_t)__half_as_ushort(h1) << 16);
}

// ---------------------------------------------------------------------------
// Split-fp16 conversion: x -> (hi, lo)
// ---------------------------------------------------------------------------
__global__ __launch_bounds__(256) void split_kernel(
    const float* __restrict__ x, __half* __restrict__ hi,
    __half* __restrict__ lo, int n4)
{
    int i = blockIdx.x * blockDim.x + threadIdx.x;
    if (i >= n4) return;
    float4 v = ((const float4*)x)[i];
    uint32_t l01, l23;
    uint32_t h01 = packsplit_h(v.x, v.y, l01);
    uint32_t h23 = packsplit_h(v.z, v.w, l23);
    ((uint2*)hi)[i] = make_uint2(h01, h23);
    ((uint2*)lo)[i] = make_uint2(l01, l23);
}

// ---------------------------------------------------------------------------
// Transpose: W[K,N] fp32 -> T[N,K] fp16 hi only
// ---------------------------------------------------------------------------
__global__ __launch_bounds__(256) void transpose_half_kernel(
    const float* __restrict__ W, __half* __restrict__ Th, int K, int N)
{
    __shared__ float t[32][33];
    int n0 = blockIdx.x * 32, k0 = blockIdx.y * 32;
    int tx = threadIdx.x, ty = threadIdx.y;   // (32, 8)
    #pragma unroll
    for (int i = 0; i < 32; i += 8)
        t[ty + i][tx] = W[(size_t)(k0 + ty + i) * N + n0 + tx];
    __syncthreads();
    #pragma unroll
    for (int i = 0; i < 32; i += 8)
        Th[(size_t)(n0 + ty + i) * K + k0 + tx] = __float2half_rn(t[tx][ty + i]);
}

// ---------------------------------------------------------------------------
// GEMM core (R12, unchanged): C = A @ B^T. A split (hi+lo), B hi-only.
// 128x128 tile, BK=32, 256 thr / 8 warps (64x32 warp tile), 2 CTAs/SM.
// 4 smem stages, one wait+sync per TWO k-tiles.
// ---------------------------------------------------------------------------
#define NKT      (Kdim / 32)       // 32
#define TILE8K   8192              // one 128x32 fp16 tile
#define STAGE_B  (3 * TILE8K)      // 24 KB per stage (Ah, Al, Bh)
#define GEMM_SMEM (4 * STAGE_B)    // 96 KB -> 2 CTAs/SM

#define GEMM_PROLOGUE_AND_MAINLOOP(AhiP, AloP, BhP)                           \
    extern __shared__ char sm[];                                              \
    const uint32_t sbase = smem_u32(sm);                                      \
    const int tid = threadIdx.x, wid = tid >> 5, lane = tid & 31;             \
    const int row0 = blockIdx.y * 128, col0 = blockIdx.x * 128;               \
    const int wm = (wid >> 2) * 64, wn = (wid & 3) * 32;                      \
    const __half* gsrc[3] = {                                                 \
        AhiP + (size_t)row0 * Kdim, AloP + (size_t)row0 * Kdim,               \
        BhP + (size_t)col0 * Kdim };                                          \
    float acc[4][4][4];                                                       \
    _Pragma("unroll")                                                         \
    for (int i = 0; i < 4; i++)                                               \
        _Pragma("unroll")                                                     \
        for (int j = 0; j < 4; j++)                                           \
            _Pragma("unroll")                                                 \
            for (int r = 0; r < 4; r++) acc[i][j][r] = 0.f;                   \
    auto LOAD = [&](int ct, int st) {                                         \
        const int kk = ct * 32;                                               \
        const uint32_t sb = sbase + st * STAGE_B;                             \
        _Pragma("unroll")                                                     \
        for (int it = 0; it < 6; it++) {                                      \
            int i   = tid + it * 256;       /* 1536 chunks */                 \
            int t   = i >> 9;                                                 \
            int rem = i & 511;                                                \
            int row = rem >> 2;                                               \
            int ch  = rem & 3;                                                \
            uint32_t so = sb + t * TILE8K + row * 64                          \
                        + ((uint32_t)(ch ^ ((row >> 1) & 3)) << 4);           \
            cp_async16(so, gsrc[t] + (size_t)row * Kdim + kk + ch * 8);       \
        }                                                                     \
    };                                                                        \
    auto COMPUTE = [&](int st) {                                              \
        const uint32_t Ah = sbase + st * STAGE_B;                             \
        const uint32_t Al = Ah + TILE8K, Bh = Ah + 2 * TILE8K;                \
        const int g = lane >> 3, lr = lane & 7;                               \
        _Pragma("unroll")                                                     \
        for (int s = 0; s < 2; s++) {                                         \
            uint32_t af[4][4], alf[4][4], bf[2][4];                           \
            _Pragma("unroll")                                                 \
            for (int i = 0; i < 4; i++) {                                     \
                int row = wm + 16 * i + (g & 1) * 8 + lr;                     \
                int ch  = 2 * s + (g >> 1);                                   \
                uint32_t off = (uint32_t)(row * 64                            \
                              + ((ch ^ ((row >> 1) & 3)) << 4));              \
                ldmx4(Ah + off, af[i]);                                       \
                ldmx4(Al + off, alf[i]);                                      \
            }                                                                 \
            _Pragma("unroll")                                                 \
            for (int h = 0; h < 2; h++) {                                     \
                int row = wn + 16 * h + (g >> 1) * 8 + lr;                    \
                int ch  = 2 * s + (g & 1);                                    \
                uint32_t off = (uint32_t)(row * 64                            \
                              + ((ch ^ ((row >> 1) & 3)) << 4));              \
                ldmx4(Bh + off, bf[h]);                                       \
            }                                                                 \
            _Pragma("unroll")                                                 \
            for (int i = 0; i < 4; i++)                                       \
                _Pragma("unroll")                                             \
                for (int j = 0; j < 4; j++) {                                 \
                    const int h = j >> 1, q = j & 1;                          \
                    mma16816(acc[i][j], af[i],  bf[h][2*q], bf[h][2*q+1]);    \
                    mma16816(acc[i][j], alf[i], bf[h][2*q], bf[h][2*q+1]);    \
                }                                                             \
        }                                                                     \
    };                                                                        \
    LOAD(0, 0); cp_commit();                                                  \
    LOAD(1, 1); cp_commit();                                                  \
    _Pragma("unroll 1")                                                       \
    for (int c = 0; c < NKT; c += 2) {                                        \
        cp_wait<0>();                                                         \
        __syncthreads();                                                      \
        if (c + 2 < NKT) { LOAD(c + 2, (c + 2) & 3); cp_commit(); }           \
        if (c + 3 < NKT) { LOAD(c + 3, (c + 3) & 3); cp_commit(); }           \
        COMPUTE(c & 3);                                                       \
        COMPUTE((c + 1) & 3);                                                 \
    }

__global__ __launch_bounds__(256, 2) void gemm_mma(
    const __half* __restrict__ Ahi, const __half* __restrict__ Alo,
    const __half* __restrict__ Bh2, float* __restrict__ C, int N)
{
    GEMM_PROLOGUE_AND_MAINLOOP(Ahi, Alo, Bh2)

    #pragma unroll
    for (int i = 0; i < 4; i++) {
        const int r = row0 + wm + 16 * i + (lane >> 2);
        #pragma unroll
        for (int j = 0; j < 4; j++) {
            const int cc = col0 + wn + 8 * j + (lane & 3) * 2;
            *(float2*)(C + (size_t)r * N + cc) =
                make_float2(acc[i][j][0], acc[i][j][1]);
            *(float2*)(C + (size_t)(r + 8) * N + cc) =
                make_float2(acc[i][j][2], acc[i][j][3]);
        }
    }
}

// Fused QKV projection: RoPE on the in-thread (2j,2j+1) pair, head transpose,
// Q pre-scale; Q and V written hi-only, K split. Permuted hd layout for Q/K.
__global__ __launch_bounds__(256, 2) void gemm_qkv_rope(
    const __half* __restrict__ Ahi, const __half* __restrict__ Alo,
    const __half* __restrict__ Bh2,
    const float* __restrict__ cosp, const float* __restrict__ sinp,
    __half* __restrict__ qh,
    __half* __restrict__ kh, __half* __restrict__ kl,
    __half* __restrict__ vh)
{
    GEMM_PROLOGUE_AND_MAINLOOP(Ahi, Alo, Bh2)

    const float SC = 0.125f * 1.4426950408889634f;   // 1/sqrt(64)*log2(e)
    #pragma unroll
    for (int j = 0; j < 4; j++) {
        const int cc   = col0 + wn + 8 * j + (lane & 3) * 2;
        const int type = cc >> 10;           // 0=q 1=k 2=v (warp-uniform)
        const int remc = cc & 1023;
        const int hh   = remc >> 6, hd = remc & 63, jp = hd >> 1;
        #pragma unroll
        for (int i = 0; i < 4; i++) {
            #pragma unroll
            for (int rr2 = 0; rr2 < 2; rr2++) {
                const int r = row0 + wm + 16 * i + (lane >> 2) + rr2 * 8;
                float e0 = acc[i][j][rr2 * 2];
                float e1 = acc[i][j][rr2 * 2 + 1];
                const int bb = r >> 11, ss = r & (Sq - 1);
                const size_t dst = ((size_t)(bb * Hq + hh) * Sq + ss) * HDq + hd;
                if (type == 2) {
                    *(uint32_t*)(vh + dst) = pack_h(e0, e1);
                    continue;
                }
                const float c  = cosp[ss * 32 + jp];
                const float sn = sinp[ss * 32 + jp];
                float a  = e0 * c  - e1 * sn;
                float b2 = e0 * sn + e1 * c;
                if (type == 0) {
                    *(uint32_t*)(qh + dst) = pack_h(a * SC, b2 * SC);
                } else {
                    uint32_t lo, hi = packsplit_h(a, b2, lo);
                    *(uint32_t*)(kh + dst) = hi;
                    *(uint32_t*)(kl + dst) = lo;
                }
            }
        }
    }
}

// ---------------------------------------------------------------------------
// Tensor-core causal flash attention (fp16).
// Q hi-only; K split; P hi-only; V hi-only (PV quantization error ~2^-12).
// CTA = 64 q, 128 thr / 4 warps (R12 pareto shape). FOUR KV buffers
// (stage = KH+KL+VH = 24 KB; Q 8 KB + 96 KB = 104 KB -> 2 CTAs/SM), ONE
// wait + sync per TWO KV tiles (paired-tile pipeline, as in the GEMM).
// ---------------------------------------------------------------------------
#define AKT 64
#define AQT 64
#define KVSTG 24576
#define ATT_SMEM (8192 + 4 * KVSTG)   // 106496

__device__ __forceinline__ uint32_t sw_off(int row, int ch) {
    return (uint32_t)(row * 128 + ((ch ^ (row & 7)) << 4));
}

__global__ __launch_bounds__(128, 2) void attn_mma(
    const __half* __restrict__ gqh,
    const __half* __restrict__ gkh, const __half* __restrict__ gkl,
    const __half* __restrict__ gvh,
    __half* __restrict__ outh, __half* __restrict__ outl)
{
    extern __shared__ char sm[];
    const uint32_t sbase = smem_u32(sm);
    const uint32_t QH = sbase;
    const int tid = threadIdx.x, wid = tid >> 5, lane = tid & 31;
    const int g = lane >> 3, lr = lane & 7;

    const int qb = (gridDim.x - 1) - blockIdx.x;     // heavy tiles first
    const int h  = blockIdx.y, b = blockIdx.z;
    const int q_base = qb * AQT;
    const int ntile = qb + 1;

    const size_t hb = (((size_t)(b * Hq + h)) * Sq) * HDq;
    const __half* kvsrc[3] = {gkh + hb, gkl + hb, gvh + hb};

    // ---- loaders -----------------------------------------------------------
    auto load_q = [&]() {
        #pragma unroll
        for (int it = 0; it < 4; it++) {
            int i = tid + it * 128;              // 512 chunks (64r x 8ch)
            int row = i >> 3, ch = i & 7;
            cp_async16(sbase + sw_off(row, ch),
                       gqh + hb + (size_t)(q_base + row) * HDq + ch * 8);
        }
    };
    auto load_kv = [&](int t, int bi) {
        const int k0 = t * AKT;
        const uint32_t sb = sbase + 8192 + (uint32_t)bi * KVSTG;
        #pragma unroll
        for (int it = 0; it < 12; it++) {
            int i = tid + it * 128;              // 1536 chunks (3 arr x 64r x 8ch)
            int arr = i >> 9, rem = i & 511;
            int row = rem >> 3, ch = rem & 7;
            cp_async16(sb + arr * 8192 + sw_off(row, ch),
                       kvsrc[arr] + (size_t)(k0 + row) * HDq + ch * 8);
        }
    };

    // per-tile compute (guarded by caller's causal skip)
    float m0 = -1e30f, m1 = -1e30f, l0 = 0.f, l1 = 0.f;
    float o[8][4];
    #pragma unroll
    for (int j = 0; j < 8; j++)
        #pragma unroll
        for (int e = 0; e < 4; e++) o[j][e] = 0.f;

    uint32_t qfh[4][4];
    const int wq = q_base + wid * 16;
    const int qg0 = wq + (lane >> 2);

    auto compute_tile = [&](int t) {
        const int k0 = t * AKT;
        if (k0 > wq + 15) return;                // fully masked for this warp
        const uint32_t BUF = sbase + 8192 + (uint32_t)(t & 3) * KVSTG;
        const uint32_t KH = BUF, KL = BUF + 8192, VH = BUF + 16384;

        // ---- scores: S = Q K^T (Qh x (Kh + Kl)) ----
        float s[8][4];
        #pragma unroll
        for (int nt = 0; nt < 8; nt++)
            #pragma unroll
            for (int e = 0; e < 4; e++) s[nt][e] = 0.f;

        #pragma unroll
        for (int kh4 = 0; kh4 < 4; kh4++) {
            #pragma unroll
            for (int s4 = 0; s4 < 4; s4++) {
                int row = 16 * kh4 + (g >> 1) * 8 + lr;
                int ch  = 2 * s4 + (g & 1);
                uint32_t kf[4], lf[4];
                ldmx4(KH + sw_off(row, ch), kf);
                ldmx4(KL + sw_off(row, ch), lf);
                mma16816(s[2*kh4],   qfh[s4], kf[0], kf[1]);
                mma16816(s[2*kh4],   qfh[s4], lf[0], lf[1]);
                mma16816(s[2*kh4+1], qfh[s4], kf[2], kf[3]);
                mma16816(s[2*kh4+1], qfh[s4], lf[2], lf[3]);
            }
        }

        // ---- causal mask (diagonal tiles only) ----
        if (k0 + AKT - 1 > wq) {
            #pragma unroll
            for (int nt = 0; nt < 8; nt++) {
                int kg = k0 + nt * 8 + (lane & 3) * 2;
                if (kg     > qg0)     s[nt][0] = -1e30f;
                if (kg + 1 > qg0)     s[nt][1] = -1e30f;
                if (kg     > qg0 + 8) s[nt][2] = -1e30f;
                if (kg + 1 > qg0 + 8) s[nt][3] = -1e30f;
            }
        }

        // ---- online softmax (exp2 domain; scale pre-folded into Q) ----
        float t0 = -1e30f, t1 = -1e30f;
        #pragma unroll
        for (int nt = 0; nt < 8; nt++) {
            t0 = fmaxf(t0, fmaxf(s[nt][0], s[nt][1]));
            t1 = fmaxf(t1, fmaxf(s[nt][2], s[nt][3]));
        }
        t0 = fmaxf(t0, __shfl_xor_sync(0xffffffffu, t0, 1));
        t0 = fmaxf(t0, __shfl_xor_sync(0xffffffffu, t0, 2));
        t1 = fmaxf(t1, __shfl_xor_sync(0xffffffffu, t1, 1));
        t1 = fmaxf(t1, __shfl_xor_sync(0xffffffffu, t1, 2));
        float mn0 = fmaxf(m0, t0), mn1 = fmaxf(m1, t1);
        float c0 = exp2f(m0 - mn0), c1 = exp2f(m1 - mn1);
        m0 = mn0; m1 = mn1;
        l0 *= c0; l1 *= c1;
        #pragma unroll
        for (int j = 0; j < 8; j++) {
            o[j][0] *= c0; o[j][1] *= c0; o[j][2] *= c1; o[j][3] *= c1;
        }
        #pragma unroll
        for (int nt = 0; nt < 8; nt++) {
            s[nt][0] = exp2f(s[nt][0] - mn0);
            s[nt][1] = exp2f(s[nt][1] - mn0);
            s[nt][2] = exp2f(s[nt][2] - mn1);
            s[nt][3] = exp2f(s[nt][3] - mn1);
            l0 += s[nt][0] + s[nt][1];
            l1 += s[nt][2] + s[nt][3];
        }

        // ---- O += P V (Ph x Vh), V via ldmatrix.trans ----
        #pragma unroll
        for (int kp = 0; kp < 4; kp++) {
            uint32_t aph[4];
            aph[0] = pack_h(s[2*kp][0],   s[2*kp][1]);
            aph[1] = pack_h(s[2*kp][2],   s[2*kp][3]);
            aph[2] = pack_h(s[2*kp+1][0], s[2*kp+1][1]);
            aph[3] = pack_h(s[2*kp+1][2], s[2*kp+1][3]);
            #pragma unroll
            for (int j2 = 0; j2 < 4; j2++) {
                int row = kp * 16 + (g & 1) * 8 + lr;
                int ch  = 2 * j2 + (g >> 1);
                uint32_t vf[4];
                ldmx4t(VH + sw_off(row, ch), vf);
                mma16816(o[2*j2],   aph, vf[0], vf[1]);
                mma16816(o[2*j2+1], aph, vf[2], vf[3]);
            }
        }
    };

    // ---- prologue: Q + KV tiles 0,1 in flight -------------------------------
    load_q(); load_kv(0, 0); cp_commit();
    if (ntile > 1) load_kv(1, 1);
    cp_commit();
    cp_wait<0>();                                // everything resident
    __syncthreads();

    #pragma unroll
    for (int s4 = 0; s4 < 4; s4++) {
        int row = wid * 16 + (g & 1) * 8 + lr;
        int ch  = 2 * s4 + (g >> 1);
        ldmx4(QH + sw_off(row, ch), qfh[s4]);
    }

    // ---- main loop: paired tiles, one wait+sync per pair ---------------------
    for (int t = 0; t < ntile; t += 2) {
        if (t) { cp_wait<0>(); __syncthreads(); }
        if (t + 2 < ntile) { load_kv(t + 2, (t + 2) & 3); cp_commit(); }
        if (t + 3 < ntile) { load_kv(t + 3, (t + 3) & 3); cp_commit(); }
        compute_tile(t);
        if (t + 1 < ntile) compute_tile(t + 1);
    }

    // ---- normalize + write split-fp16 [b,s,D] (out-proj A operand) ----
    float ls0 = l0 + __shfl_xor_sync(0xffffffffu, l0, 1);
    ls0 += __shfl_xor_sync(0xffffffffu, ls0, 2);
    float ls1 = l1 + __shfl_xor_sync(0xffffffffu, l1, 1);
    ls1 += __shfl_xor_sync(0xffffffffu, ls1, 2);
    const float inv0 = 1.f / ls0, inv1 = 1.f / ls1;

    const size_t base0 = ((size_t)b * Sq + qg0) * Dq + h * HDq;
    const size_t base1 = ((size_t)b * Sq + qg0 + 8) * Dq + h * HDq;
    #pragma unroll
    for (int j = 0; j < 8; j++) {
        int cc = j * 8 + (lane & 3) * 2;
        uint32_t lo0, lo1;
        uint32_t hi0 = packsplit_h(o[j][0] * inv0, o[j][1] * inv0, lo0);
        uint32_t hi1 = packsplit_h(o[j][2] * inv1, o[j][3] * inv1, lo1);
        *(uint32_t*)(outh + base0 + cc) = hi0;
        *(uint32_t*)(outl + base0 + cc) = lo0;
        *(uint32_t*)(outh + base1 + cc) = hi1;
        *(uint32_t*)(outl + base1 + cc) = lo1;
    }
}

// ---------------------------------------------------------------------------
// Launch
// ---------------------------------------------------------------------------
extern "C" void kernel_launch(void* const* d_in, const int* in_sizes, int n_in,
                              void* d_out, int out_size)
{
    const float* x    = (const float*)d_in[0];
    const float* cosp = (const float*)d_in[1];
    const float* sinp = (const float*)d_in[2];
    // d_in[3] = mask: causal -1e9 — handled analytically, never read.
    const float* Wqkv = (const float*)d_in[4];
    const float* Wout = (const float*)d_in[5];
    float* out = (float*)d_out;

    __half *p_xh, *p_xl, *p_w1h, *p_w2h, *p_ah, *p_al;
    __half *p_qh, *p_kh, *p_kl, *p_vh;
    cudaGetSymbolAddress((void**)&p_xh,  g_xh);
    cudaGetSymbolAddress((void**)&p_xl,  g_xl);
    cudaGetSymbolAddress((void**)&p_w1h, g_w1h);
    cudaGetSymbolAddress((void**)&p_w2h, g_w2h);
    cudaGetSymbolAddress((void**)&p_ah,  g_ah);
    cudaGetSymbolAddress((void**)&p_al,  g_al);
    cudaGetSymbolAddress((void**)&p_qh,  g_qh);
    cudaGetSymbolAddress((void**)&p_kh,  g_kh);
    cudaGetSymbolAddress((void**)&p_kl,  g_kl);
    cudaGetSymbolAddress((void**)&p_vh,  g_vh);

    cudaFuncSetAttribute(gemm_mma, cudaFuncAttributeMaxDynamicSharedMemorySize,
                         GEMM_SMEM);
    cudaFuncSetAttribute(gemm_qkv_rope, cudaFuncAttributeMaxDynamicSharedMemorySize,
                         GEMM_SMEM);
    cudaFuncSetAttribute(attn_mma, cudaFuncAttributeMaxDynamicSharedMemorySize,
                         ATT_SMEM);

    // 0) Conversions: x split-fp16; weights transposed fp16 hi-only
    {
        int n4 = Mrows * Kdim / 4;
        split_kernel<<<(n4 + 255) / 256, 256>>>(x, p_xh, p_xl, n4);
        dim3 blk(32, 8);
        transpose_half_kernel<<<dim3(3 * Dq / 32, Kdim / 32), blk>>>(Wqkv, p_w1h, Kdim, 3 * Dq);
        transpose_half_kernel<<<dim3(Dq / 32, Kdim / 32), blk>>>(Wout, p_w2h, Kdim, Dq);
    }
    // 1) QKV projection + fused RoPE/transpose/split (mma.sync fp16)
    {
        dim3 grid(3 * Dq / 128, Mrows / 128);
        gemm_qkv_rope<<<grid, 256, GEMM_SMEM>>>(p_xh, p_xl, p_w1h,
                                                cosp, sinp,
                                                p_qh, p_kh, p_kl, p_vh);
    }
    // 2) Tensor-core causal flash attention
    {
        dim3 grid(Sq / AQT, Hq, Bq);
        attn_mma<<<grid, 128, ATT_SMEM>>>(p_qh, p_kh, p_kl, p_vh,
                                          p_ah, p_al);
    }
    // 3) Output projection (mma.sync fp16)
    {
        dim3 grid(Dq / 128, Mrows / 128);
        gemm_mma<<<grid, 256, GEMM_SMEM>>>(p_ah, p_al, p_w2h, out, Dq);
    }
}

// round 15
// speedup vs baseline: 1.2183x; 1.0793x over previous
#include <cuda_runtime.h>
#include <cuda_fp16.h>
#include <math.h>
#include <cstdint>

// Problem shape (fixed by the dataset)
#define Bq  4
#define Sq  2048
#define Dq  1024
#define Hq  16
#define HDq 64
#define Mrows (Bq*Sq)          // 8192
#define Kdim 1024

// ---------------------------------------------------------------------------
// Scratch (device globals). fp16 asymmetric scheme:
//   x, k stored SPLIT (hi+lo); weights / q / p / v / attn-out HI-ONLY.
// ---------------------------------------------------------------------------
__device__ __half g_xh [(size_t)Mrows * Kdim];
__device__ __half g_xl [(size_t)Mrows * Kdim];
__device__ __half g_w1h[(size_t)3 * Dq * Kdim];          // WqkvT hi only
__device__ __half g_w2h[(size_t)Dq * Kdim];              // WoutT hi only
__device__ __half g_ah [(size_t)Mrows * Kdim];           // attn out hi, [b,s,D]

#define QKV_ELEMS ((size_t)Bq*Hq*Sq*HDq)
// Q/K use PERMUTED head-dim layout (pos 2j = rope[j], 2j+1 = rope[32+j]);
// QK^T invariant under common permutation of the contraction axis.
__device__ __half g_qh[QKV_ELEMS];                       // Q hi only
__device__ __half g_kh[QKV_ELEMS];
__device__ __half g_kl[QKV_ELEMS];
__device__ __half g_vh[QKV_ELEMS];                       // V hi only

// ---------------------------------------------------------------------------
// PTX helpers (plain sm_80-era features only; toolchain targets sm_103 w/o 'a')
// ---------------------------------------------------------------------------
__device__ __forceinline__ uint32_t smem_u32(const void* p) {
    uint32_t a;
    asm("{ .reg .u64 t; cvta.to.shared.u64 t, %1; cvt.u32.u64 %0, t; }"
        : "=r"(a) : "l"(p));
    return a;
}
__device__ __forceinline__ void cp_async16(uint32_t s, const void* g) {
    asm volatile("cp.async.cg.shared.global [%0], [%1], 16;" :: "r"(s), "l"(g));
}
__device__ __forceinline__ void cp_commit() {
    asm volatile("cp.async.commit_group;" ::: "memory");
}
template<int N> __device__ __forceinline__ void cp_wait() {
    asm volatile("cp.async.wait_group %0;" :: "n"(N) : "memory");
}
__device__ __forceinline__ void ldmx4(uint32_t addr, uint32_t* r) {
    asm volatile("ldmatrix.sync.aligned.m8n8.x4.shared.b16 {%0,%1,%2,%3}, [%4];"
        : "=r"(r[0]), "=r"(r[1]), "=r"(r[2]), "=r"(r[3]) : "r"(addr));
}
__device__ __forceinline__ void ldmx4t(uint32_t addr, uint32_t* r) {
    asm volatile("ldmatrix.sync.aligned.m8n8.x4.trans.shared.b16 {%0,%1,%2,%3}, [%4];"
        : "=r"(r[0]), "=r"(r[1]), "=r"(r[2]), "=r"(r[3]) : "r"(addr));
}
__device__ __forceinline__ void mma16816(float* d, const uint32_t* a,
                                         uint32_t b0, uint32_t b1) {
    asm volatile(
        "mma.sync.aligned.m16n8k16.row.col.f32.f16.f16.f32 "
        "{%0,%1,%2,%3}, {%4,%5,%6,%7}, {%8,%9}, {%0,%1,%2,%3};"
        : "+f"(d[0]), "+f"(d[1]), "+f"(d[2]), "+f"(d[3])
        : "r"(a[0]), "r"(a[1]), "r"(a[2]), "r"(a[3]), "r"(b0), "r"(b1));
}
__device__ __forceinline__ uint32_t pack_h(float x0, float x1) {
    __half2 h = __floats2half2_rn(x0, x1);
    return *(uint32_t*)&h;
}
// pack two fp32 into fp16x2 hi; residual lo via out-param
__device__ __forceinline__ uint32_t packsplit_h(float x0, float x1, uint32_t& lo) {
    __half h0 = __float2half_rn(x0), h1 = __float2half_rn(x1);
    lo = pack_h(x0 - __half2float(h0), x1 - __half2float(h1));
    return (uint32_t)__half_as_ushort(h0) | ((uint32_t)__half_as_ushort(h1) << 16);
}

// ---------------------------------------------------------------------------
// Split-fp16 conversion: x -> (hi, lo)
// ---------------------------------------------------------------------------
__global__ __launch_bounds__(256) void split_kernel(
    const float* __restrict__ x, __half* __restrict__ hi,
    __half* __restrict__ lo, int n4)
{
    int i = blockIdx.x * blockDim.x + threadIdx.x;
    if (i >= n4) return;
    float4 v = ((const float4*)x)[i];
    uint32_t l01, l23;
    uint32_t h01 = packsplit_h(v.x, v.y, l01);
    uint32_t h23 = packsplit_h(v.z, v.w, l23);
    ((uint2*)hi)[i] = make_uint2(h01, h23);
    ((uint2*)lo)[i] = make_uint2(l01, l23);
}

// ---------------------------------------------------------------------------
// Transpose: W[K,N] fp32 -> T[N,K] fp16 hi only
// ---------------------------------------------------------------------------
__global__ __launch_bounds__(256) void transpose_half_kernel(
    const float* __restrict__ W, __half* __restrict__ Th, int K, int N)
{
    __shared__ float t[32][33];
    int n0 = blockIdx.x * 32, k0 = blockIdx.y * 32;
    int tx = threadIdx.x, ty = threadIdx.y;   // (32, 8)
    #pragma unroll
    for (int i = 0; i < 32; i += 8)
        t[ty + i][tx] = W[(size_t)(k0 + ty + i) * N + n0 + tx];
    __syncthreads();
    #pragma unroll
    for (int i = 0; i < 32; i += 8)
        Th[(size_t)(n0 + ty + i) * K + k0 + tx] = __float2half_rn(t[tx][ty + i]);
}

// ---------------------------------------------------------------------------
// 2-product GEMM core (R12 verified): A split (hi+lo), B hi-only.
// 128x128 tile, BK=32, 256 thr / 8 warps (64x32 warp tile), 2 CTAs/SM,
// 4 smem stages, one wait+sync per TWO k-tiles. Used for QKV projection.
// ---------------------------------------------------------------------------
#define NKT      (Kdim / 32)       // 32
#define TILE8K   8192              // one 128x32 fp16 tile
#define STAGE_B  (3 * TILE8K)      // 24 KB per stage (Ah, Al, Bh)
#define GEMM_SMEM (4 * STAGE_B)    // 96 KB -> 2 CTAs/SM

#define GEMM_PROLOGUE_AND_MAINLOOP(AhiP, AloP, BhP)                           \
    extern __shared__ char sm[];                                              \
    const uint32_t sbase = smem_u32(sm);                                      \
    const int tid = threadIdx.x, wid = tid >> 5, lane = tid & 31;             \
    const int row0 = blockIdx.y * 128, col0 = blockIdx.x * 128;               \
    const int wm = (wid >> 2) * 64, wn = (wid & 3) * 32;                      \
    const __half* gsrc[3] = {                                                 \
        AhiP + (size_t)row0 * Kdim, AloP + (size_t)row0 * Kdim,               \
        BhP + (size_t)col0 * Kdim };                                          \
    float acc[4][4][4];                                                       \
    _Pragma("unroll")                                                         \
    for (int i = 0; i < 4; i++)                                               \
        _Pragma("unroll")                                                     \
        for (int j = 0; j < 4; j++)                                           \
            _Pragma("unroll")                                                 \
            for (int r = 0; r < 4; r++) acc[i][j][r] = 0.f;                   \
    auto LOAD = [&](int ct, int st) {                                         \
        const int kk = ct * 32;                                               \
        const uint32_t sb = sbase + st * STAGE_B;                             \
        _Pragma("unroll")                                                     \
        for (int it = 0; it < 6; it++) {                                      \
            int i   = tid + it * 256;       /* 1536 chunks */                 \
            int t   = i >> 9;                                                 \
            int rem = i & 511;                                                \
            int row = rem >> 2;                                               \
            int ch  = rem & 3;                                                \
            uint32_t so = sb + t * TILE8K + row * 64                          \
                        + ((uint32_t)(ch ^ ((row >> 1) & 3)) << 4);           \
            cp_async16(so, gsrc[t] + (size_t)row * Kdim + kk + ch * 8);       \
        }                                                                     \
    };                                                                        \
    auto COMPUTE = [&](int st) {                                              \
        const uint32_t Ah = sbase + st * STAGE_B;                             \
        const uint32_t Al = Ah + TILE8K, Bh = Ah + 2 * TILE8K;                \
        const int g = lane >> 3, lr = lane & 7;                               \
        _Pragma("unroll")                                                     \
        for (int s = 0; s < 2; s++) {                                         \
            uint32_t af[4][4], alf[4][4], bf[2][4];                           \
            _Pragma("unroll")                                                 \
            for (int i = 0; i < 4; i++) {                                     \
                int row = wm + 16 * i + (g & 1) * 8 + lr;                     \
                int ch  = 2 * s + (g >> 1);                                   \
                uint32_t off = (uint32_t)(row * 64                            \
                              + ((ch ^ ((row >> 1) & 3)) << 4));              \
                ldmx4(Ah + off, af[i]);                                       \
                ldmx4(Al + off, alf[i]);                                      \
            }                                                                 \
            _Pragma("unroll")                                                 \
            for (int h = 0; h < 2; h++) {                                     \
                int row = wn + 16 * h + (g >> 1) * 8 + lr;                    \
                int ch  = 2 * s + (g & 1);                                    \
                uint32_t off = (uint32_t)(row * 64                            \
                              + ((ch ^ ((row >> 1) & 3)) << 4));              \
                ldmx4(Bh + off, bf[h]);                                       \
            }                                                                 \
            _Pragma("unroll")                                                 \
            for (int i = 0; i < 4; i++)                                       \
                _Pragma("unroll")                                             \
                for (int j = 0; j < 4; j++) {                                 \
                    const int h = j >> 1, q = j & 1;                          \
                    mma16816(acc[i][j], af[i],  bf[h][2*q], bf[h][2*q+1]);    \
                    mma16816(acc[i][j], alf[i], bf[h][2*q], bf[h][2*q+1]);    \
                }                                                             \
        }                                                                     \
    };                                                                        \
    LOAD(0, 0); cp_commit();                                                  \
    LOAD(1, 1); cp_commit();                                                  \
    _Pragma("unroll 1")                                                       \
    for (int c = 0; c < NKT; c += 2) {                                        \
        cp_wait<0>();                                                         \
        __syncthreads();                                                      \
        if (c + 2 < NKT) { LOAD(c + 2, (c + 2) & 3); cp_commit(); }           \
        if (c + 3 < NKT) { LOAD(c + 3, (c + 3) & 3); cp_commit(); }           \
        COMPUTE(c & 3);                                                       \
        COMPUTE((c + 1) & 3);                                                 \
    }

// Fused QKV projection: RoPE on the in-thread (2j,2j+1) pair, head transpose,
// Q pre-scale; Q and V written hi-only, K split. Permuted hd layout for Q/K.
__global__ __launch_bounds__(256, 2) void gemm_qkv_rope(
    const __half* __restrict__ Ahi, const __half* __restrict__ Alo,
    const __half* __restrict__ Bh2,
    const float* __restrict__ cosp, const float* __restrict__ sinp,
    __half* __restrict__ qh,
    __half* __restrict__ kh, __half* __restrict__ kl,
    __half* __restrict__ vh)
{
    GEMM_PROLOGUE_AND_MAINLOOP(Ahi, Alo, Bh2)

    const float SC = 0.125f * 1.4426950408889634f;   // 1/sqrt(64)*log2(e)
    #pragma unroll
    for (int j = 0; j < 4; j++) {
        const int cc   = col0 + wn + 8 * j + (lane & 3) * 2;
        const int type = cc >> 10;           // 0=q 1=k 2=v (warp-uniform)
        const int remc = cc & 1023;
        const int hh   = remc >> 6, hd = remc & 63, jp = hd >> 1;
        #pragma unroll
        for (int i = 0; i < 4; i++) {
            #pragma unroll
            for (int rr2 = 0; rr2 < 2; rr2++) {
                const int r = row0 + wm + 16 * i + (lane >> 2) + rr2 * 8;
                float e0 = acc[i][j][rr2 * 2];
                float e1 = acc[i][j][rr2 * 2 + 1];
                const int bb = r >> 11, ss = r & (Sq - 1);
                const size_t dst = ((size_t)(bb * Hq + hh) * Sq + ss) * HDq + hd;
                if (type == 2) {
                    *(uint32_t*)(vh + dst) = pack_h(e0, e1);
                    continue;
                }
                const float c  = cosp[ss * 32 + jp];
                const float sn = sinp[ss * 32 + jp];
                float a  = e0 * c  - e1 * sn;
                float b2 = e0 * sn + e1 * c;
                if (type == 0) {
                    *(uint32_t*)(qh + dst) = pack_h(a * SC, b2 * SC);
                } else {
                    uint32_t lo, hi = packsplit_h(a, b2, lo);
                    *(uint32_t*)(kh + dst) = hi;
                    *(uint32_t*)(kl + dst) = lo;
                }
            }
        }
    }
}

// ---------------------------------------------------------------------------
// 1-product GEMM (out-projection): C = Ah @ Bh^T, both hi-only fp16.
// Same pipeline shape; stage = Ah + Bh = 16 KB, 4 stages = 64 KB, 2 CTAs/SM.
// ---------------------------------------------------------------------------
#define STAGE1P   (2 * TILE8K)     // 16 KB
#define GEMM1P_SMEM (4 * STAGE1P)  // 64 KB

__global__ __launch_bounds__(256, 2) void gemm_mma_1p(
    const __half* __restrict__ Ah2, const __half* __restrict__ Bh2,
    float* __restrict__ C, int N)
{
    extern __shared__ char sm[];
    const uint32_t sbase = smem_u32(sm);
    const int tid = threadIdx.x, wid = tid >> 5, lane = tid & 31;
    const int row0 = blockIdx.y * 128, col0 = blockIdx.x * 128;
    const int wm = (wid >> 2) * 64, wn = (wid & 3) * 32;
    const __half* gsrc[2] = {
        Ah2 + (size_t)row0 * Kdim, Bh2 + (size_t)col0 * Kdim };

    float acc[4][4][4];
    #pragma unroll
    for (int i = 0; i < 4; i++)
        #pragma unroll
        for (int j = 0; j < 4; j++)
            #pragma unroll
            for (int r = 0; r < 4; r++) acc[i][j][r] = 0.f;

    auto LOAD = [&](int ct, int st) {
        const int kk = ct * 32;
        const uint32_t sb = sbase + st * STAGE1P;
        #pragma unroll
        for (int it = 0; it < 4; it++) {
            int i   = tid + it * 256;       // 1024 chunks
            int t   = i >> 9;
            int rem = i & 511;
            int row = rem >> 2;
            int ch  = rem & 3;
            uint32_t so = sb + t * TILE8K + row * 64
                        + ((uint32_t)(ch ^ ((row >> 1) & 3)) << 4);
            cp_async16(so, gsrc[t] + (size_t)row * Kdim + kk + ch * 8);
        }
    };
    auto COMPUTE = [&](int st) {
        const uint32_t Ah = sbase + st * STAGE1P;
        const uint32_t Bh = Ah + TILE8K;
        const int g = lane >> 3, lr = lane & 7;
        #pragma unroll
        for (int s = 0; s < 2; s++) {
            uint32_t af[4][4], bf[2][4];
            #pragma unroll
            for (int i = 0; i < 4; i++) {
                int row = wm + 16 * i + (g & 1) * 8 + lr;
                int ch  = 2 * s + (g >> 1);
                uint32_t off = (uint32_t)(row * 64
                              + ((ch ^ ((row >> 1) & 3)) << 4));
                ldmx4(Ah + off, af[i]);
            }
            #pragma unroll
            for (int h = 0; h < 2; h++) {
                int row = wn + 16 * h + (g >> 1) * 8 + lr;
                int ch  = 2 * s + (g & 1);
                uint32_t off = (uint32_t)(row * 64
                              + ((ch ^ ((row >> 1) & 3)) << 4));
                ldmx4(Bh + off, bf[h]);
            }
            #pragma unroll
            for (int i = 0; i < 4; i++)
                #pragma unroll
                for (int j = 0; j < 4; j++) {
                    const int h = j >> 1, q = j & 1;
                    mma16816(acc[i][j], af[i], bf[h][2*q], bf[h][2*q+1]);
                }
        }
    };

    LOAD(0, 0); cp_commit();
    LOAD(1, 1); cp_commit();
    #pragma unroll 1
    for (int c = 0; c < NKT; c += 2) {
        cp_wait<0>();
        __syncthreads();
        if (c + 2 < NKT) { LOAD(c + 2, (c + 2) & 3); cp_commit(); }
        if (c + 3 < NKT) { LOAD(c + 3, (c + 3) & 3); cp_commit(); }
        COMPUTE(c & 3);
        COMPUTE((c + 1) & 3);
    }

    #pragma unroll
    for (int i = 0; i < 4; i++) {
        const int r = row0 + wm + 16 * i + (lane >> 2);
        #pragma unroll
        for (int j = 0; j < 4; j++) {
            const int cc = col0 + wn + 8 * j + (lane & 3) * 2;
            *(float2*)(C + (size_t)r * N + cc) =
                make_float2(acc[i][j][0], acc[i][j][1]);
            *(float2*)(C + (size_t)(r + 8) * N + cc) =
                make_float2(acc[i][j][2], acc[i][j][3]);
        }
    }
}

// ---------------------------------------------------------------------------
// Tensor-core causal flash attention (fp16). Q hi; K split; P hi; V hi.
// CTA = 64 q, 128 thr / 4 warps. FOUR KV buffers (24 KB each), paired-tile
// pipeline. Output written HI-ONLY (out-proj is 1-product).
// ---------------------------------------------------------------------------
#define AKT 64
#define AQT 64
#define KVSTG 24576
#define ATT_SMEM (8192 + 4 * KVSTG)   // 106496

__device__ __forceinline__ uint32_t sw_off(int row, int ch) {
    return (uint32_t)(row * 128 + ((ch ^ (row & 7)) << 4));
}

__global__ __launch_bounds__(128, 2) void attn_mma(
    const __half* __restrict__ gqh,
    const __half* __restrict__ gkh, const __half* __restrict__ gkl,
    const __half* __restrict__ gvh,
    __half* __restrict__ outh)
{
    extern __shared__ char sm[];
    const uint32_t sbase = smem_u32(sm);
    const uint32_t QH = sbase;
    const int tid = threadIdx.x, wid = tid >> 5, lane = tid & 31;
    const int g = lane >> 3, lr = lane & 7;

    const int qb = (gridDim.x - 1) - blockIdx.x;     // heavy tiles first
    const int h  = blockIdx.y, b = blockIdx.z;
    const int q_base = qb * AQT;
    const int ntile = qb + 1;

    const size_t hb = (((size_t)(b * Hq + h)) * Sq) * HDq;
    const __half* kvsrc[3] = {gkh + hb, gkl + hb, gvh + hb};

    auto load_q = [&]() {
        #pragma unroll
        for (int it = 0; it < 4; it++) {
            int i = tid + it * 128;
            int row = i >> 3, ch = i & 7;
            cp_async16(sbase + sw_off(row, ch),
                       gqh + hb + (size_t)(q_base + row) * HDq + ch * 8);
        }
    };
    auto load_kv = [&](int t, int bi) {
        const int k0 = t * AKT;
        const uint32_t sb = sbase + 8192 + (uint32_t)bi * KVSTG;
        #pragma unroll
        for (int it = 0; it < 12; it++) {
            int i = tid + it * 128;
            int arr = i >> 9, rem = i & 511;
            int row = rem >> 3, ch = rem & 7;
            cp_async16(sb + arr * 8192 + sw_off(row, ch),
                       kvsrc[arr] + (size_t)(k0 + row) * HDq + ch * 8);
        }
    };

    float m0 = -1e30f, m1 = -1e30f, l0 = 0.f, l1 = 0.f;
    float o[8][4];
    #pragma unroll
    for (int j = 0; j < 8; j++)
        #pragma unroll
        for (int e = 0; e < 4; e++) o[j][e] = 0.f;

    uint32_t qfh[4][4];
    const int wq = q_base + wid * 16;
    const int qg0 = wq + (lane >> 2);

    auto compute_tile = [&](int t) {
        const int k0 = t * AKT;
        if (k0 > wq + 15) return;
        const uint32_t BUF = sbase + 8192 + (uint32_t)(t & 3) * KVSTG;
        const uint32_t KH = BUF, KL = BUF + 8192, VH = BUF + 16384;

        float s[8][4];
        #pragma unroll
        for (int nt = 0; nt < 8; nt++)
            #pragma unroll
            for (int e = 0; e < 4; e++) s[nt][e] = 0.f;

        #pragma unroll
        for (int kh4 = 0; kh4 < 4; kh4++) {
            #pragma unroll
            for (int s4 = 0; s4 < 4; s4++) {
                int row = 16 * kh4 + (g >> 1) * 8 + lr;
                int ch  = 2 * s4 + (g & 1);
                uint32_t kf[4], lf[4];
                ldmx4(KH + sw_off(row, ch), kf);
                ldmx4(KL + sw_off(row, ch), lf);
                mma16816(s[2*kh4],   qfh[s4], kf[0], kf[1]);
                mma16816(s[2*kh4],   qfh[s4], lf[0], lf[1]);
                mma16816(s[2*kh4+1], qfh[s4], kf[2], kf[3]);
                mma16816(s[2*kh4+1], qfh[s4], lf[2], lf[3]);
            }
        }

        if (k0 + AKT - 1 > wq) {
            #pragma unroll
            for (int nt = 0; nt < 8; nt++) {
                int kg = k0 + nt * 8 + (lane & 3) * 2;
                if (kg     > qg0)     s[nt][0] = -1e30f;
                if (kg + 1 > qg0)     s[nt][1] = -1e30f;
                if (kg     > qg0 + 8) s[nt][2] = -1e30f;
                if (kg + 1 > qg0 + 8) s[nt][3] = -1e30f;
            }
        }

        float t0 = -1e30f, t1 = -1e30f;
        #pragma unroll
        for (int nt = 0; nt < 8; nt++) {
            t0 = fmaxf(t0, fmaxf(s[nt][0], s[nt][1]));
            t1 = fmaxf(t1, fmaxf(s[nt][2], s[nt][3]));
        }
        t0 = fmaxf(t0, __shfl_xor_sync(0xffffffffu, t0, 1));
        t0 = fmaxf(t0, __shfl_xor_sync(0xffffffffu, t0, 2));
        t1 = fmaxf(t1, __shfl_xor_sync(0xffffffffu, t1, 1));
        t1 = fmaxf(t1, __shfl_xor_sync(0xffffffffu, t1, 2));
        float mn0 = fmaxf(m0, t0), mn1 = fmaxf(m1, t1);
        float c0 = exp2f(m0 - mn0), c1 = exp2f(m1 - mn1);
        m0 = mn0; m1 = mn1;
        l0 *= c0; l1 *= c1;
        #pragma unroll
        for (int j = 0; j < 8; j++) {
            o[j][0] *= c0; o[j][1] *= c0; o[j][2] *= c1; o[j][3] *= c1;
        }
        #pragma unroll
        for (int nt = 0; nt < 8; nt++) {
            s[nt][0] = exp2f(s[nt][0] - mn0);
            s[nt][1] = exp2f(s[nt][1] - mn0);
            s[nt][2] = exp2f(s[nt][2] - mn1);
            s[nt][3] = exp2f(s[nt][3] - mn1);
            l0 += s[nt][0] + s[nt][1];
            l1 += s[nt][2] + s[nt][3];
        }

        #pragma unroll
        for (int kp = 0; kp < 4; kp++) {
            uint32_t aph[4];
            aph[0] = pack_h(s[2*kp][0],   s[2*kp][1]);
            aph[1] = pack_h(s[2*kp][2],   s[2*kp][3]);
            aph[2] = pack_h(s[2*kp+1][0], s[2*kp+1][1]);
            aph[3] = pack_h(s[2*kp+1][2], s[2*kp+1][3]);
            #pragma unroll
            for (int j2 = 0; j2 < 4; j2++) {
                int row = kp * 16 + (g & 1) * 8 + lr;
                int ch  = 2 * j2 + (g >> 1);
                uint32_t vf[4];
                ldmx4t(VH + sw_off(row, ch), vf);
                mma16816(o[2*j2],   aph, vf[0], vf[1]);
                mma16816(o[2*j2+1], aph, vf[2], vf[3]);
            }
        }
    };

    load_q(); load_kv(0, 0); cp_commit();
    if (ntile > 1) load_kv(1, 1);
    cp_commit();
    cp_wait<0>();
    __syncthreads();

    #pragma unroll
    for (int s4 = 0; s4 < 4; s4++) {
        int row = wid * 16 + (g & 1) * 8 + lr;
        int ch  = 2 * s4 + (g >> 1);
        ldmx4(QH + sw_off(row, ch), qfh[s4]);
    }

    for (int t = 0; t < ntile; t += 2) {
        if (t) { cp_wait<0>(); __syncthreads(); }
        if (t + 2 < ntile) { load_kv(t + 2, (t + 2) & 3); cp_commit(); }
        if (t + 3 < ntile) { load_kv(t + 3, (t + 3) & 3); cp_commit(); }
        compute_tile(t);
        if (t + 1 < ntile) compute_tile(t + 1);
    }

    // ---- normalize + write fp16 hi [b,s,D] (out-proj A operand) ----
    float ls0 = l0 + __shfl_xor_sync(0xffffffffu, l0, 1);
    ls0 += __shfl_xor_sync(0xffffffffu, ls0, 2);
    float ls1 = l1 + __shfl_xor_sync(0xffffffffu, l1, 1);
    ls1 += __shfl_xor_sync(0xffffffffu, ls1, 2);
    const float inv0 = 1.f / ls0, inv1 = 1.f / ls1;

    const size_t base0 = ((size_t)b * Sq + qg0) * Dq + h * HDq;
    const size_t base1 = ((size_t)b * Sq + qg0 + 8) * Dq + h * HDq;
    #pragma unroll
    for (int j = 0; j < 8; j++) {
        int cc = j * 8 + (lane & 3) * 2;
        *(uint32_t*)(outh + base0 + cc) = pack_h(o[j][0] * inv0, o[j][1] * inv0);
        *(uint32_t*)(outh + base1 + cc) = pack_h(o[j][2] * inv1, o[j][3] * inv1);
    }
}

// ---------------------------------------------------------------------------
// Launch
// ---------------------------------------------------------------------------
extern "C" void kernel_launch(void* const* d_in, const int* in_sizes, int n_in,
                              void* d_out, int out_size)
{
    const float* x    = (const float*)d_in[0];
    const float* cosp = (const float*)d_in[1];
    const float* sinp = (const float*)d_in[2];
    // d_in[3] = mask: causal -1e9 — handled analytically, never read.
    const float* Wqkv = (const float*)d_in[4];
    const float* Wout = (const float*)d_in[5];
    float* out = (float*)d_out;

    __half *p_xh, *p_xl, *p_w1h, *p_w2h, *p_ah;
    __half *p_qh, *p_kh, *p_kl, *p_vh;
    cudaGetSymbolAddress((void**)&p_xh,  g_xh);
    cudaGetSymbolAddress((void**)&p_xl,  g_xl);
    cudaGetSymbolAddress((void**)&p_w1h, g_w1h);
    cudaGetSymbolAddress((void**)&p_w2h, g_w2h);
    cudaGetSymbolAddress((void**)&p_ah,  g_ah);
    cudaGetSymbolAddress((void**)&p_qh,  g_qh);
    cudaGetSymbolAddress((void**)&p_kh,  g_kh);
    cudaGetSymbolAddress((void**)&p_kl,  g_kl);
    cudaGetSymbolAddress((void**)&p_vh,  g_vh);

    cudaFuncSetAttribute(gemm_qkv_rope, cudaFuncAttributeMaxDynamicSharedMemorySize,
                         GEMM_SMEM);
    cudaFuncSetAttribute(gemm_mma_1p, cudaFuncAttributeMaxDynamicSharedMemorySize,
                         GEMM1P_SMEM);
    cudaFuncSetAttribute(attn_mma, cudaFuncAttributeMaxDynamicSharedMemorySize,
                         ATT_SMEM);

    // 0) Conversions: x split-fp16; weights transposed fp16 hi-only
    {
        int n4 = Mrows * Kdim / 4;
        split_kernel<<<(n4 + 255) / 256, 256>>>(x, p_xh, p_xl, n4);
        dim3 blk(32, 8);
        transpose_half_kernel<<<dim3(3 * Dq / 32, Kdim / 32), blk>>>(Wqkv, p_w1h, Kdim, 3 * Dq);
        transpose_half_kernel<<<dim3(Dq / 32, Kdim / 32), blk>>>(Wout, p_w2h, Kdim, Dq);
    }
    // 1) QKV projection + fused RoPE/transpose/split (mma.sync fp16, 2-product)
    {
        dim3 grid(3 * Dq / 128, Mrows / 128);
        gemm_qkv_rope<<<grid, 256, GEMM_SMEM>>>(p_xh, p_xl, p_w1h,
                                                cosp, sinp,
                                                p_qh, p_kh, p_kl, p_vh);
    }
    // 2) Tensor-core causal flash attention (emits fp16 hi only)
    {
        dim3 grid(Sq / AQT, Hq, Bq);
        attn_mma<<<grid, 128, ATT_SMEM>>>(p_qh, p_kh, p_kl, p_vh, p_ah);
    }
    // 3) Output projection (mma.sync fp16, 1-product)
    {
        dim3 grid(Dq / 128, Mrows / 128);
        gemm_mma_1p<<<grid, 256, GEMM1P_SMEM>>>(p_ah, p_w2h, out, Dq);
    }
}

// round 16
// speedup vs baseline: 1.5126x; 1.2416x over previous
#include <cuda_runtime.h>
#include <cuda_fp16.h>
#include <math.h>
#include <cstdint>

// Problem shape (fixed by the dataset)
#define Bq  4
#define Sq  2048
#define Dq  1024
#define Hq  16
#define HDq 64
#define Mrows (Bq*Sq)          // 8192
#define Kdim 1024

// ---------------------------------------------------------------------------
// Scratch (device globals). fp16 scheme:
//   K stored SPLIT (hi+lo) — logits need the precision;
//   x / weights / q / p / v / attn-out HI-ONLY (each drop ~2^-12 incoherent).
// ---------------------------------------------------------------------------
__device__ __half g_xh [(size_t)Mrows * Kdim];
__device__ __half g_w1h[(size_t)3 * Dq * Kdim];          // WqkvT hi only
__device__ __half g_w2h[(size_t)Dq * Kdim];              // WoutT hi only
__device__ __half g_ah [(size_t)Mrows * Kdim];           // attn out hi, [b,s,D]

#define QKV_ELEMS ((size_t)Bq*Hq*Sq*HDq)
// Q/K use PERMUTED head-dim layout (pos 2j = rope[j], 2j+1 = rope[32+j]);
// QK^T invariant under common permutation of the contraction axis.
__device__ __half g_qh[QKV_ELEMS];                       // Q hi only
__device__ __half g_kh[QKV_ELEMS];
__device__ __half g_kl[QKV_ELEMS];
__device__ __half g_vh[QKV_ELEMS];                       // V hi only

// ---------------------------------------------------------------------------
// PTX helpers (plain sm_80-era features only; toolchain targets sm_103 w/o 'a')
// ---------------------------------------------------------------------------
__device__ __forceinline__ uint32_t smem_u32(const void* p) {
    uint32_t a;
    asm("{ .reg .u64 t; cvta.to.shared.u64 t, %1; cvt.u32.u64 %0, t; }"
        : "=r"(a) : "l"(p));
    return a;
}
__device__ __forceinline__ void cp_async16(uint32_t s, const void* g) {
    asm volatile("cp.async.cg.shared.global [%0], [%1], 16;" :: "r"(s), "l"(g));
}
__device__ __forceinline__ void cp_commit() {
    asm volatile("cp.async.commit_group;" ::: "memory");
}
template<int N> __device__ __forceinline__ void cp_wait() {
    asm volatile("cp.async.wait_group %0;" :: "n"(N) : "memory");
}
__device__ __forceinline__ void ldmx4(uint32_t addr, uint32_t* r) {
    asm volatile("ldmatrix.sync.aligned.m8n8.x4.shared.b16 {%0,%1,%2,%3}, [%4];"
        : "=r"(r[0]), "=r"(r[1]), "=r"(r[2]), "=r"(r[3]) : "r"(addr));
}
__device__ __forceinline__ void ldmx4t(uint32_t addr, uint32_t* r) {
    asm volatile("ldmatrix.sync.aligned.m8n8.x4.trans.shared.b16 {%0,%1,%2,%3}, [%4];"
        : "=r"(r[0]), "=r"(r[1]), "=r"(r[2]), "=r"(r[3]) : "r"(addr));
}
__device__ __forceinline__ void mma16816(float* d, const uint32_t* a,
                                         uint32_t b0, uint32_t b1) {
    asm volatile(
        "mma.sync.aligned.m16n8k16.row.col.f32.f16.f16.f32 "
        "{%0,%1,%2,%3}, {%4,%5,%6,%7}, {%8,%9}, {%0,%1,%2,%3};"
        : "+f"(d[0]), "+f"(d[1]), "+f"(d[2]), "+f"(d[3])
        : "r"(a[0]), "r"(a[1]), "r"(a[2]), "r"(a[3]), "r"(b0), "r"(b1));
}
__device__ __forceinline__ uint32_t pack_h(float x0, float x1) {
    __half2 h = __floats2half2_rn(x0, x1);
    return *(uint32_t*)&h;
}
// pack two fp32 into fp16x2 hi; residual lo via out-param
__device__ __forceinline__ uint32_t packsplit_h(float x0, float x1, uint32_t& lo) {
    __half h0 = __float2half_rn(x0), h1 = __float2half_rn(x1);
    lo = pack_h(x0 - __half2float(h0), x1 - __half2float(h1));
    return (uint32_t)__half_as_ushort(h0) | ((uint32_t)__half_as_ushort(h1) << 16);
}

// ---------------------------------------------------------------------------
// fp32 -> fp16 (hi only) conversion
// ---------------------------------------------------------------------------
__global__ __launch_bounds__(256) void convert_half_kernel(
    const float* __restrict__ x, __half* __restrict__ hi, int n4)
{
    int i = blockIdx.x * blockDim.x + threadIdx.x;
    if (i >= n4) return;
    float4 v = ((const float4*)x)[i];
    ((uint2*)hi)[i] = make_uint2(pack_h(v.x, v.y), pack_h(v.z, v.w));
}

// ---------------------------------------------------------------------------
// Transpose: W[K,N] fp32 -> T[N,K] fp16 hi only
// ---------------------------------------------------------------------------
__global__ __launch_bounds__(256) void transpose_half_kernel(
    const float* __restrict__ W, __half* __restrict__ Th, int K, int N)
{
    __shared__ float t[32][33];
    int n0 = blockIdx.x * 32, k0 = blockIdx.y * 32;
    int tx = threadIdx.x, ty = threadIdx.y;   // (32, 8)
    #pragma unroll
    for (int i = 0; i < 32; i += 8)
        t[ty + i][tx] = W[(size_t)(k0 + ty + i) * N + n0 + tx];
    __syncthreads();
    #pragma unroll
    for (int i = 0; i < 32; i += 8)
        Th[(size_t)(n0 + ty + i) * K + k0 + tx] = __float2half_rn(t[tx][ty + i]);
}

// ---------------------------------------------------------------------------
// 1-product GEMM core: C = Ah @ Bh^T, both hi-only fp16. 128x128 tile,
// BK=32, 256 thr / 8 warps (64x32 warp tile), 2 CTAs/SM, 4 smem stages
// (16 KB each = 64 KB), one wait+sync per TWO k-tiles.
// ---------------------------------------------------------------------------
#define NKT      (Kdim / 32)       // 32
#define TILE8K   8192              // one 128x32 fp16 tile
#define STAGE1P   (2 * TILE8K)     // 16 KB (Ah, Bh)
#define GEMM1P_SMEM (4 * STAGE1P)  // 64 KB

#define GEMM1P_PROLOGUE_AND_MAINLOOP(AhP, BhP)                                \
    extern __shared__ char sm[];                                              \
    const uint32_t sbase = smem_u32(sm);                                      \
    const int tid = threadIdx.x, wid = tid >> 5, lane = tid & 31;             \
    const int row0 = blockIdx.y * 128, col0 = blockIdx.x * 128;               \
    const int wm = (wid >> 2) * 64, wn = (wid & 3) * 32;                      \
    const __half* gsrc[2] = {                                                 \
        AhP + (size_t)row0 * Kdim, BhP + (size_t)col0 * Kdim };               \
    float acc[4][4][4];                                                       \
    _Pragma("unroll")                                                         \
    for (int i = 0; i < 4; i++)                                               \
        _Pragma("unroll")                                                     \
        for (int j = 0; j < 4; j++)                                           \
            _Pragma("unroll")                                                 \
            for (int r = 0; r < 4; r++) acc[i][j][r] = 0.f;                   \
    auto LOAD = [&](int ct, int st) {                                         \
        const int kk = ct * 32;                                               \
        const uint32_t sb = sbase + st * STAGE1P;                             \
        _Pragma("unroll")                                                     \
        for (int it = 0; it < 4; it++) {                                      \
            int i   = tid + it * 256;       /* 1024 chunks */                 \
            int t   = i >> 9;                                                 \
            int rem = i & 511;                                                \
            int row = rem >> 2;                                               \
            int ch  = rem & 3;                                                \
            uint32_t so = sb + t * TILE8K + row * 64                          \
                        + ((uint32_t)(ch ^ ((row >> 1) & 3)) << 4);           \
            cp_async16(so, gsrc[t] + (size_t)row * Kdim + kk + ch * 8);       \
        }                                                                     \
    };                                                                        \
    auto COMPUTE = [&](int st) {                                              \
        const uint32_t Ah = sbase + st * STAGE1P;                             \
        const uint32_t Bh = Ah + TILE8K;                                      \
        const int g = lane >> 3, lr = lane & 7;                               \
        _Pragma("unroll")                                                     \
        for (int s = 0; s < 2; s++) {                                         \
            uint32_t af[4][4], bf[2][4];                                      \
            _Pragma("unroll")                                                 \
            for (int i = 0; i < 4; i++) {                                     \
                int row = wm + 16 * i + (g & 1) * 8 + lr;                     \
                int ch  = 2 * s + (g >> 1);                                   \
                uint32_t off = (uint32_t)(row * 64                            \
                              + ((ch ^ ((row >> 1) & 3)) << 4));              \
                ldmx4(Ah + off, af[i]);                                       \
            }                                                                 \
            _Pragma("unroll")                                                 \
            for (int h = 0; h < 2; h++) {                                     \
                int row = wn + 16 * h + (g >> 1) * 8 + lr;                    \
                int ch  = 2 * s + (g & 1);                                    \
                uint32_t off = (uint32_t)(row * 64                            \
                              + ((ch ^ ((row >> 1) & 3)) << 4));              \
                ldmx4(Bh + off, bf[h]);                                       \
            }                                                                 \
            _Pragma("unroll")                                                 \
            for (int i = 0; i < 4; i++)                                       \
                _Pragma("unroll")                                             \
                for (int j = 0; j < 4; j++) {                                 \
                    const int h = j >> 1, q = j & 1;                          \
                    mma16816(acc[i][j], af[i], bf[h][2*q], bf[h][2*q+1]);     \
                }                                                             \
        }                                                                     \
    };                                                                        \
    LOAD(0, 0); cp_commit();                                                  \
    LOAD(1, 1); cp_commit();                                                  \
    _Pragma("unroll 1")                                                       \
    for (int c = 0; c < NKT; c += 2) {                                        \
        cp_wait<0>();                                                         \
        __syncthreads();                                                      \
        if (c + 2 < NKT) { LOAD(c + 2, (c + 2) & 3); cp_commit(); }           \
        if (c + 3 < NKT) { LOAD(c + 3, (c + 3) & 3); cp_commit(); }           \
        COMPUTE(c & 3);                                                       \
        COMPUTE((c + 1) & 3);                                                 \
    }

// Out-projection: plain fp32 store epilogue.
__global__ __launch_bounds__(256, 2) void gemm_mma_1p(
    const __half* __restrict__ Ah2, const __half* __restrict__ Bh2,
    float* __restrict__ C, int N)
{
    GEMM1P_PROLOGUE_AND_MAINLOOP(Ah2, Bh2)

    #pragma unroll
    for (int i = 0; i < 4; i++) {
        const int r = row0 + wm + 16 * i + (lane >> 2);
        #pragma unroll
        for (int j = 0; j < 4; j++) {
            const int cc = col0 + wn + 8 * j + (lane & 3) * 2;
            *(float2*)(C + (size_t)r * N + cc) =
                make_float2(acc[i][j][0], acc[i][j][1]);
            *(float2*)(C + (size_t)(r + 8) * N + cc) =
                make_float2(acc[i][j][2], acc[i][j][3]);
        }
    }
}

// Fused QKV projection (now 1-product): RoPE on the in-thread (2j,2j+1) pair,
// head transpose, Q pre-scale; Q and V hi-only, K split. Permuted hd layout.
__global__ __launch_bounds__(256, 2) void gemm_qkv_rope(
    const __half* __restrict__ Ah2, const __half* __restrict__ Bh2,
    const float* __restrict__ cosp, const float* __restrict__ sinp,
    __half* __restrict__ qh,
    __half* __restrict__ kh, __half* __restrict__ kl,
    __half* __restrict__ vh)
{
    GEMM1P_PROLOGUE_AND_MAINLOOP(Ah2, Bh2)

    const float SC = 0.125f * 1.4426950408889634f;   // 1/sqrt(64)*log2(e)
    #pragma unroll
    for (int j = 0; j < 4; j++) {
        const int cc   = col0 + wn + 8 * j + (lane & 3) * 2;
        const int type = cc >> 10;           // 0=q 1=k 2=v (warp-uniform)
        const int remc = cc & 1023;
        const int hh   = remc >> 6, hd = remc & 63, jp = hd >> 1;
        #pragma unroll
        for (int i = 0; i < 4; i++) {
            #pragma unroll
            for (int rr2 = 0; rr2 < 2; rr2++) {
                const int r = row0 + wm + 16 * i + (lane >> 2) + rr2 * 8;
                float e0 = acc[i][j][rr2 * 2];
                float e1 = acc[i][j][rr2 * 2 + 1];
                const int bb = r >> 11, ss = r & (Sq - 1);
                const size_t dst = ((size_t)(bb * Hq + hh) * Sq + ss) * HDq + hd;
                if (type == 2) {
                    *(uint32_t*)(vh + dst) = pack_h(e0, e1);
                    continue;
                }
                const float c  = cosp[ss * 32 + jp];
                const float sn = sinp[ss * 32 + jp];
                float a  = e0 * c  - e1 * sn;
                float b2 = e0 * sn + e1 * c;
                if (type == 0) {
                    *(uint32_t*)(qh + dst) = pack_h(a * SC, b2 * SC);
                } else {
                    uint32_t lo, hi = packsplit_h(a, b2, lo);
                    *(uint32_t*)(kh + dst) = hi;
                    *(uint32_t*)(kl + dst) = lo;
                }
            }
        }
    }
}

// ---------------------------------------------------------------------------
// Tensor-core causal flash attention (fp16, unchanged from R15).
// Q hi; K split; P hi; V hi. CTA = 64 q, 128 thr / 4 warps. FOUR KV buffers
// (24 KB each), paired-tile pipeline. Output hi-only.
// ---------------------------------------------------------------------------
#define AKT 64
#define AQT 64
#define KVSTG 24576
#define ATT_SMEM (8192 + 4 * KVSTG)   // 106496

__device__ __forceinline__ uint32_t sw_off(int row, int ch) {
    return (uint32_t)(row * 128 + ((ch ^ (row & 7)) << 4));
}

__global__ __launch_bounds__(128, 2) void attn_mma(
    const __half* __restrict__ gqh,
    const __half* __restrict__ gkh, const __half* __restrict__ gkl,
    const __half* __restrict__ gvh,
    __half* __restrict__ outh)
{
    extern __shared__ char sm[];
    const uint32_t sbase = smem_u32(sm);
    const uint32_t QH = sbase;
    const int tid = threadIdx.x, wid = tid >> 5, lane = tid & 31;
    const int g = lane >> 3, lr = lane & 7;

    const int qb = (gridDim.x - 1) - blockIdx.x;     // heavy tiles first
    const int h  = blockIdx.y, b = blockIdx.z;
    const int q_base = qb * AQT;
    const int ntile = qb + 1;

    const size_t hb = (((size_t)(b * Hq + h)) * Sq) * HDq;
    const __half* kvsrc[3] = {gkh + hb, gkl + hb, gvh + hb};

    auto load_q = [&]() {
        #pragma unroll
        for (int it = 0; it < 4; it++) {
            int i = tid + it * 128;
            int row = i >> 3, ch = i & 7;
            cp_async16(sbase + sw_off(row, ch),
                       gqh + hb + (size_t)(q_base + row) * HDq + ch * 8);
        }
    };
    auto load_kv = [&](int t, int bi) {
        const int k0 = t * AKT;
        const uint32_t sb = sbase + 8192 + (uint32_t)bi * KVSTG;
        #pragma unroll
        for (int it = 0; it < 12; it++) {
            int i = tid + it * 128;
            int arr = i >> 9, rem = i & 511;
            int row = rem >> 3, ch = rem & 7;
            cp_async16(sb + arr * 8192 + sw_off(row, ch),
                       kvsrc[arr] + (size_t)(k0 + row) * HDq + ch * 8);
        }
    };

    float m0 = -1e30f, m1 = -1e30f, l0 = 0.f, l1 = 0.f;
    float o[8][4];
    #pragma unroll
    for (int j = 0; j < 8; j++)
        #pragma unroll
        for (int e = 0; e < 4; e++) o[j][e] = 0.f;

    uint32_t qfh[4][4];
    const int wq = q_base + wid * 16;
    const int qg0 = wq + (lane >> 2);

    auto compute_tile = [&](int t) {
        const int k0 = t * AKT;
        if (k0 > wq + 15) return;
        const uint32_t BUF = sbase + 8192 + (uint32_t)(t & 3) * KVSTG;
        const uint32_t KH = BUF, KL = BUF + 8192, VH = BUF + 16384;

        float s[8][4];
        #pragma unroll
        for (int nt = 0; nt < 8; nt++)
            #pragma unroll
            for (int e = 0; e < 4; e++) s[nt][e] = 0.f;

        #pragma unroll
        for (int kh4 = 0; kh4 < 4; kh4++) {
            #pragma unroll
            for (int s4 = 0; s4 < 4; s4++) {
                int row = 16 * kh4 + (g >> 1) * 8 + lr;
                int ch  = 2 * s4 + (g & 1);
                uint32_t kf[4], lf[4];
                ldmx4(KH + sw_off(row, ch), kf);
                ldmx4(KL + sw_off(row, ch), lf);
                mma16816(s[2*kh4],   qfh[s4], kf[0], kf[1]);
                mma16816(s[2*kh4],   qfh[s4], lf[0], lf[1]);
                mma16816(s[2*kh4+1], qfh[s4], kf[2], kf[3]);
                mma16816(s[2*kh4+1], qfh[s4], lf[2], lf[3]);
            }
        }

        if (k0 + AKT - 1 > wq) {
            #pragma unroll
            for (int nt = 0; nt < 8; nt++) {
                int kg = k0 + nt * 8 + (lane & 3) * 2;
                if (kg     > qg0)     s[nt][0] = -1e30f;
                if (kg + 1 > qg0)     s[nt][1] = -1e30f;
                if (kg     > qg0 + 8) s[nt][2] = -1e30f;
                if (kg + 1 > qg0 + 8) s[nt][3] = -1e30f;
            }
        }

        float t0 = -1e30f, t1 = -1e30f;
        #pragma unroll
        for (int nt = 0; nt < 8; nt++) {
            t0 = fmaxf(t0, fmaxf(s[nt][0], s[nt][1]));
            t1 = fmaxf(t1, fmaxf(s[nt][2], s[nt][3]));
        }
        t0 = fmaxf(t0, __shfl_xor_sync(0xffffffffu, t0, 1));
        t0 = fmaxf(t0, __shfl_xor_sync(0xffffffffu, t0, 2));
        t1 = fmaxf(t1, __shfl_xor_sync(0xffffffffu, t1, 1));
        t1 = fmaxf(t1, __shfl_xor_sync(0xffffffffu, t1, 2));
        float mn0 = fmaxf(m0, t0), mn1 = fmaxf(m1, t1);
        float c0 = exp2f(m0 - mn0), c1 = exp2f(m1 - mn1);
        m0 = mn0; m1 = mn1;
        l0 *= c0; l1 *= c1;
        #pragma unroll
        for (int j = 0; j < 8; j++) {
            o[j][0] *= c0; o[j][1] *= c0; o[j][2] *= c1; o[j][3] *= c1;
        }
        #pragma unroll
        for (int nt = 0; nt < 8; nt++) {
            s[nt][0] = exp2f(s[nt][0] - mn0);
            s[nt][1] = exp2f(s[nt][1] - mn0);
            s[nt][2] = exp2f(s[nt][2] - mn1);
            s[nt][3] = exp2f(s[nt][3] - mn1);
            l0 += s[nt][0] + s[nt][1];
            l1 += s[nt][2] + s[nt][3];
        }

        #pragma unroll
        for (int kp = 0; kp < 4; kp++) {
            uint32_t aph[4];
            aph[0] = pack_h(s[2*kp][0],   s[2*kp][1]);
            aph[1] = pack_h(s[2*kp][2],   s[2*kp][3]);
            aph[2] = pack_h(s[2*kp+1][0], s[2*kp+1][1]);
            aph[3] = pack_h(s[2*kp+1][2], s[2*kp+1][3]);
            #pragma unroll
            for (int j2 = 0; j2 < 4; j2++) {
                int row = kp * 16 + (g & 1) * 8 + lr;
                int ch  = 2 * j2 + (g >> 1);
                uint32_t vf[4];
                ldmx4t(VH + sw_off(row, ch), vf);
                mma16816(o[2*j2],   aph, vf[0], vf[1]);
                mma16816(o[2*j2+1], aph, vf[2], vf[3]);
            }
        }
    };

    load_q(); load_kv(0, 0); cp_commit();
    if (ntile > 1) load_kv(1, 1);
    cp_commit();
    cp_wait<0>();
    __syncthreads();

    #pragma unroll
    for (int s4 = 0; s4 < 4; s4++) {
        int row = wid * 16 + (g & 1) * 8 + lr;
        int ch  = 2 * s4 + (g >> 1);
        ldmx4(QH + sw_off(row, ch), qfh[s4]);
    }

    for (int t = 0; t < ntile; t += 2) {
        if (t) { cp_wait<0>(); __syncthreads(); }
        if (t + 2 < ntile) { load_kv(t + 2, (t + 2) & 3); cp_commit(); }
        if (t + 3 < ntile) { load_kv(t + 3, (t + 3) & 3); cp_commit(); }
        compute_tile(t);
        if (t + 1 < ntile) compute_tile(t + 1);
    }

    // ---- normalize + write fp16 hi [b,s,D] (out-proj A operand) ----
    float ls0 = l0 + __shfl_xor_sync(0xffffffffu, l0, 1);
    ls0 += __shfl_xor_sync(0xffffffffu, ls0, 2);
    float ls1 = l1 + __shfl_xor_sync(0xffffffffu, l1, 1);
    ls1 += __shfl_xor_sync(0xffffffffu, ls1, 2);
    const float inv0 = 1.f / ls0, inv1 = 1.f / ls1;

    const size_t base0 = ((size_t)b * Sq + qg0) * Dq + h * HDq;
    const size_t base1 = ((size_t)b * Sq + qg0 + 8) * Dq + h * HDq;
    #pragma unroll
    for (int j = 0; j < 8; j++) {
        int cc = j * 8 + (lane & 3) * 2;
        *(uint32_t*)(outh + base0 + cc) = pack_h(o[j][0] * inv0, o[j][1] * inv0);
        *(uint32_t*)(outh + base1 + cc) = pack_h(o[j][2] * inv1, o[j][3] * inv1);
    }
}

// ---------------------------------------------------------------------------
// Launch
// ---------------------------------------------------------------------------
extern "C" void kernel_launch(void* const* d_in, const int* in_sizes, int n_in,
                              void* d_out, int out_size)
{
    const float* x    = (const float*)d_in[0];
    const float* cosp = (const float*)d_in[1];
    const float* sinp = (const float*)d_in[2];
    // d_in[3] = mask: causal -1e9 — handled analytically, never read.
    const float* Wqkv = (const float*)d_in[4];
    const float* Wout = (const float*)d_in[5];
    float* out = (float*)d_out;

    __half *p_xh, *p_w1h, *p_w2h, *p_ah;
    __half *p_qh, *p_kh, *p_kl, *p_vh;
    cudaGetSymbolAddress((void**)&p_xh,  g_xh);
    cudaGetSymbolAddress((void**)&p_w1h, g_w1h);
    cudaGetSymbolAddress((void**)&p_w2h, g_w2h);
    cudaGetSymbolAddress((void**)&p_ah,  g_ah);
    cudaGetSymbolAddress((void**)&p_qh,  g_qh);
    cudaGetSymbolAddress((void**)&p_kh,  g_kh);
    cudaGetSymbolAddress((void**)&p_kl,  g_kl);
    cudaGetSymbolAddress((void**)&p_vh,  g_vh);

    cudaFuncSetAttribute(gemm_qkv_rope, cudaFuncAttributeMaxDynamicSharedMemorySize,
                         GEMM1P_SMEM);
    cudaFuncSetAttribute(gemm_mma_1p, cudaFuncAttributeMaxDynamicSharedMemorySize,
                         GEMM1P_SMEM);
    cudaFuncSetAttribute(attn_mma, cudaFuncAttributeMaxDynamicSharedMemorySize,
                         ATT_SMEM);

    // 0) Conversions: x and weights -> fp16 hi-only
    {
        int n4 = Mrows * Kdim / 4;
        convert_half_kernel<<<(n4 + 255) / 256, 256>>>(x, p_xh, n4);
        dim3 blk(32, 8);
        transpose_half_kernel<<<dim3(3 * Dq / 32, Kdim / 32), blk>>>(Wqkv, p_w1h, Kdim, 3 * Dq);
        transpose_half_kernel<<<dim3(Dq / 32, Kdim / 32), blk>>>(Wout, p_w2h, Kdim, Dq);
    }
    // 1) QKV projection + fused RoPE/transpose (mma.sync fp16, 1-product)
    {
        dim3 grid(3 * Dq / 128, Mrows / 128);
        gemm_qkv_rope<<<grid, 256, GEMM1P_SMEM>>>(p_xh, p_w1h, cosp, sinp,
                                                  p_qh, p_kh, p_kl, p_vh);
    }
    // 2) Tensor-core causal flash attention (emits fp16 hi only)
    {
        dim3 grid(Sq / AQT, Hq, Bq);
        attn_mma<<<grid, 128, ATT_SMEM>>>(p_qh, p_kh, p_kl, p_vh, p_ah);
    }
    // 3) Output projection (mma.sync fp16, 1-product)
    {
        dim3 grid(Dq / 128, Mrows / 128);
        gemm_mma_1p<<<grid, 256, GEMM1P_SMEM>>>(p_ah, p_w2h, out, Dq);
    }
}

// round 17
// speedup vs baseline: 1.7247x; 1.1402x over previous
#include <cuda_runtime.h>
#include <cuda_fp16.h>
#include <math.h>
#include <cstdint>

// Problem shape (fixed by the dataset)
#define Bq  4
#define Sq  2048
#define Dq  1024
#define Hq  16
#define HDq 64
#define Mrows (Bq*Sq)          // 8192
#define Kdim 1024

// ---------------------------------------------------------------------------
// Scratch (device globals). Pure fp16 hi-only everywhere; the calibrated
// quadrature error model puts total rel_err ~6.8e-4 (< 1e-3 gate, 1.47x).
// ---------------------------------------------------------------------------
__device__ __half g_xh [(size_t)Mrows * Kdim];
__device__ __half g_w1h[(size_t)3 * Dq * Kdim];          // WqkvT hi only
__device__ __half g_w2h[(size_t)Dq * Kdim];              // WoutT hi only
__device__ __half g_ah [(size_t)Mrows * Kdim];           // attn out hi, [b,s,D]

#define QKV_ELEMS ((size_t)Bq*Hq*Sq*HDq)
// Q/K use PERMUTED head-dim layout (pos 2j = rope[j], 2j+1 = rope[32+j]);
// QK^T invariant under common permutation of the contraction axis.
__device__ __half g_qh[QKV_ELEMS];
__device__ __half g_kh[QKV_ELEMS];
__device__ __half g_vh[QKV_ELEMS];

// ---------------------------------------------------------------------------
// PTX helpers (plain sm_80-era features only; toolchain targets sm_103 w/o 'a')
// ---------------------------------------------------------------------------
__device__ __forceinline__ uint32_t smem_u32(const void* p) {
    uint32_t a;
    asm("{ .reg .u64 t; cvta.to.shared.u64 t, %1; cvt.u32.u64 %0, t; }"
        : "=r"(a) : "l"(p));
    return a;
}
__device__ __forceinline__ void cp_async16(uint32_t s, const void* g) {
    asm volatile("cp.async.cg.shared.global [%0], [%1], 16;" :: "r"(s), "l"(g));
}
__device__ __forceinline__ void cp_commit() {
    asm volatile("cp.async.commit_group;" ::: "memory");
}
template<int N> __device__ __forceinline__ void cp_wait() {
    asm volatile("cp.async.wait_group %0;" :: "n"(N) : "memory");
}
__device__ __forceinline__ void ldmx4(uint32_t addr, uint32_t* r) {
    asm volatile("ldmatrix.sync.aligned.m8n8.x4.shared.b16 {%0,%1,%2,%3}, [%4];"
        : "=r"(r[0]), "=r"(r[1]), "=r"(r[2]), "=r"(r[3]) : "r"(addr));
}
__device__ __forceinline__ void ldmx4t(uint32_t addr, uint32_t* r) {
    asm volatile("ldmatrix.sync.aligned.m8n8.x4.trans.shared.b16 {%0,%1,%2,%3}, [%4];"
        : "=r"(r[0]), "=r"(r[1]), "=r"(r[2]), "=r"(r[3]) : "r"(addr));
}
__device__ __forceinline__ void mma16816(float* d, const uint32_t* a,
                                         uint32_t b0, uint32_t b1) {
    asm volatile(
        "mma.sync.aligned.m16n8k16.row.col.f32.f16.f16.f32 "
        "{%0,%1,%2,%3}, {%4,%5,%6,%7}, {%8,%9}, {%0,%1,%2,%3};"
        : "+f"(d[0]), "+f"(d[1]), "+f"(d[2]), "+f"(d[3])
        : "r"(a[0]), "r"(a[1]), "r"(a[2]), "r"(a[3]), "r"(b0), "r"(b1));
}
__device__ __forceinline__ uint32_t pack_h(float x0, float x1) {
    __half2 h = __floats2half2_rn(x0, x1);
    return *(uint32_t*)&h;
}

// ---------------------------------------------------------------------------
// fp32 -> fp16 (hi only) conversion
// ---------------------------------------------------------------------------
__global__ __launch_bounds__(256) void convert_half_kernel(
    const float* __restrict__ x, __half* __restrict__ hi, int n4)
{
    int i = blockIdx.x * blockDim.x + threadIdx.x;
    if (i >= n4) return;
    float4 v = ((const float4*)x)[i];
    ((uint2*)hi)[i] = make_uint2(pack_h(v.x, v.y), pack_h(v.z, v.w));
}

// ---------------------------------------------------------------------------
// Transpose: W[K,N] fp32 -> T[N,K] fp16 hi only
// ---------------------------------------------------------------------------
__global__ __launch_bounds__(256) void transpose_half_kernel(
    const float* __restrict__ W, __half* __restrict__ Th, int K, int N)
{
    __shared__ float t[32][33];
    int n0 = blockIdx.x * 32, k0 = blockIdx.y * 32;
    int tx = threadIdx.x, ty = threadIdx.y;   // (32, 8)
    #pragma unroll
    for (int i = 0; i < 32; i += 8)
        t[ty + i][tx] = W[(size_t)(k0 + ty + i) * N + n0 + tx];
    __syncthreads();
    #pragma unroll
    for (int i = 0; i < 32; i += 8)
        Th[(size_t)(n0 + ty + i) * K + k0 + tx] = __float2half_rn(t[tx][ty + i]);
}

// ---------------------------------------------------------------------------
// 1-product GEMM core: C = Ah @ Bh^T, both hi-only fp16. 128x128 tile,
// BK=32, 256 thr / 8 warps (64x32 warp tile), 2 CTAs/SM, 4 smem stages
// (16 KB each = 64 KB), one wait+sync per TWO k-tiles.
// ---------------------------------------------------------------------------
#define NKT      (Kdim / 32)       // 32
#define TILE8K   8192              // one 128x32 fp16 tile
#define STAGE1P   (2 * TILE8K)     // 16 KB (Ah, Bh)
#define GEMM1P_SMEM (4 * STAGE1P)  // 64 KB

#define GEMM1P_PROLOGUE_AND_MAINLOOP(AhP, BhP)                                \
    extern __shared__ char sm[];                                              \
    const uint32_t sbase = smem_u32(sm);                                      \
    const int tid = threadIdx.x, wid = tid >> 5, lane = tid & 31;             \
    const int row0 = blockIdx.y * 128, col0 = blockIdx.x * 128;               \
    const int wm = (wid >> 2) * 64, wn = (wid & 3) * 32;                      \
    const __half* gsrc[2] = {                                                 \
        AhP + (size_t)row0 * Kdim, BhP + (size_t)col0 * Kdim };               \
    float acc[4][4][4];                                                       \
    _Pragma("unroll")                                                         \
    for (int i = 0; i < 4; i++)                                               \
        _Pragma("unroll")                                                     \
        for (int j = 0; j < 4; j++)                                           \
            _Pragma("unroll")                                                 \
            for (int r = 0; r < 4; r++) acc[i][j][r] = 0.f;                   \
    auto LOAD = [&](int ct, int st) {                                         \
        const int kk = ct * 32;                                               \
        const uint32_t sb = sbase + st * STAGE1P;                             \
        _Pragma("unroll")                                                     \
        for (int it = 0; it < 4; it++) {                                      \
            int i   = tid + it * 256;       /* 1024 chunks */                 \
            int t   = i >> 9;                                                 \
            int rem = i & 511;                                                \
            int row = rem >> 2;                                               \
            int ch  = rem & 3;                                                \
            uint32_t so = sb + t * TILE8K + row * 64                          \
                        + ((uint32_t)(ch ^ ((row >> 1) & 3)) << 4);           \
            cp_async16(so, gsrc[t] + (size_t)row * Kdim + kk + ch * 8);       \
        }                                                                     \
    };                                                                        \
    auto COMPUTE = [&](int st) {                                              \
        const uint32_t Ah = sbase + st * STAGE1P;                             \
        const uint32_t Bh = Ah + TILE8K;                                      \
        const int g = lane >> 3, lr = lane & 7;                               \
        _Pragma("unroll")                                                     \
        for (int s = 0; s < 2; s++) {                                         \
            uint32_t af[4][4], bf[2][4];                                      \
            _Pragma("unroll")                                                 \
            for (int i = 0; i < 4; i++) {                                     \
                int row = wm + 16 * i + (g & 1) * 8 + lr;                     \
                int ch  = 2 * s + (g >> 1);                                   \
                uint32_t off = (uint32_t)(row * 64                            \
                              + ((ch ^ ((row >> 1) & 3)) << 4));              \
                ldmx4(Ah + off, af[i]);                                       \
            }                                                                 \
            _Pragma("unroll")                                                 \
            for (int h = 0; h < 2; h++) {                                     \
                int row = wn + 16 * h + (g >> 1) * 8 + lr;                    \
                int ch  = 2 * s + (g & 1);                                    \
                uint32_t off = (uint32_t)(row * 64                            \
                              + ((ch ^ ((row >> 1) & 3)) << 4));              \
                ldmx4(Bh + off, bf[h]);                                       \
            }                                                                 \
            _Pragma("unroll")                                                 \
            for (int i = 0; i < 4; i++)                                       \
                _Pragma("unroll")                                             \
                for (int j = 0; j < 4; j++) {                                 \
                    const int h = j >> 1, q = j & 1;                          \
                    mma16816(acc[i][j], af[i], bf[h][2*q], bf[h][2*q+1]);     \
                }                                                             \
        }                                                                     \
    };                                                                        \
    LOAD(0, 0); cp_commit();                                                  \
    LOAD(1, 1); cp_commit();                                                  \
    _Pragma("unroll 1")                                                       \
    for (int c = 0; c < NKT; c += 2) {                                        \
        cp_wait<0>();                                                         \
        __syncthreads();                                                      \
        if (c + 2 < NKT) { LOAD(c + 2, (c + 2) & 3); cp_commit(); }           \
        if (c + 3 < NKT) { LOAD(c + 3, (c + 3) & 3); cp_commit(); }           \
        COMPUTE(c & 3);                                                       \
        COMPUTE((c + 1) & 3);                                                 \
    }

// Out-projection: plain fp32 store epilogue.
__global__ __launch_bounds__(256, 2) void gemm_mma_1p(
    const __half* __restrict__ Ah2, const __half* __restrict__ Bh2,
    float* __restrict__ C, int N)
{
    GEMM1P_PROLOGUE_AND_MAINLOOP(Ah2, Bh2)

    #pragma unroll
    for (int i = 0; i < 4; i++) {
        const int r = row0 + wm + 16 * i + (lane >> 2);
        #pragma unroll
        for (int j = 0; j < 4; j++) {
            const int cc = col0 + wn + 8 * j + (lane & 3) * 2;
            *(float2*)(C + (size_t)r * N + cc) =
                make_float2(acc[i][j][0], acc[i][j][1]);
            *(float2*)(C + (size_t)(r + 8) * N + cc) =
                make_float2(acc[i][j][2], acc[i][j][3]);
        }
    }
}

// Fused QKV projection (1-product): RoPE on the in-thread (2j,2j+1) pair,
// head transpose, Q pre-scale; all outputs hi-only. Permuted hd layout.
__global__ __launch_bounds__(256, 2) void gemm_qkv_rope(
    const __half* __restrict__ Ah2, const __half* __restrict__ Bh2,
    const float* __restrict__ cosp, const float* __restrict__ sinp,
    __half* __restrict__ qh, __half* __restrict__ kh, __half* __restrict__ vh)
{
    GEMM1P_PROLOGUE_AND_MAINLOOP(Ah2, Bh2)

    const float SC = 0.125f * 1.4426950408889634f;   // 1/sqrt(64)*log2(e)
    #pragma unroll
    for (int j = 0; j < 4; j++) {
        const int cc   = col0 + wn + 8 * j + (lane & 3) * 2;
        const int type = cc >> 10;           // 0=q 1=k 2=v (warp-uniform)
        const int remc = cc & 1023;
        const int hh   = remc >> 6, hd = remc & 63, jp = hd >> 1;
        __half* dstp = (type == 0) ? qh : (type == 1) ? kh : vh;
        #pragma unroll
        for (int i = 0; i < 4; i++) {
            #pragma unroll
            for (int rr2 = 0; rr2 < 2; rr2++) {
                const int r = row0 + wm + 16 * i + (lane >> 2) + rr2 * 8;
                float e0 = acc[i][j][rr2 * 2];
                float e1 = acc[i][j][rr2 * 2 + 1];
                const int bb = r >> 11, ss = r & (Sq - 1);
                const size_t dst = ((size_t)(bb * Hq + hh) * Sq + ss) * HDq + hd;
                if (type != 2) {
                    const float c  = cosp[ss * 32 + jp];
                    const float sn = sinp[ss * 32 + jp];
                    float a  = e0 * c  - e1 * sn;
                    float b2 = e0 * sn + e1 * c;
                    if (type == 0) { a *= SC; b2 *= SC; }
                    e0 = a; e1 = b2;
                }
                *(uint32_t*)(dstp + dst) = pack_h(e0, e1);
            }
        }
    }
}

// ---------------------------------------------------------------------------
// Tensor-core causal flash attention (pure fp16 1-product).
// Q/K/V/P all hi-only. CTA = 64 q, 128 thr / 4 warps. FOUR KV buffers of
// 16 KB (KH+VH); SMEM = 8 + 64 = 72 KB -> THREE CTAs/SM (12 warps hide the
// softmax scalar phase). Paired-tile pipeline, one wait+sync per two tiles.
// ---------------------------------------------------------------------------
#define AKT 64
#define AQT 64
#define KVSTG 16384
#define ATT_SMEM (8192 + 4 * KVSTG)   // 73728

__device__ __forceinline__ uint32_t sw_off(int row, int ch) {
    return (uint32_t)(row * 128 + ((ch ^ (row & 7)) << 4));
}

__global__ __launch_bounds__(128, 3) void attn_mma(
    const __half* __restrict__ gqh, const __half* __restrict__ gkh,
    const __half* __restrict__ gvh, __half* __restrict__ outh)
{
    extern __shared__ char sm[];
    const uint32_t sbase = smem_u32(sm);
    const uint32_t QH = sbase;
    const int tid = threadIdx.x, wid = tid >> 5, lane = tid & 31;
    const int g = lane >> 3, lr = lane & 7;

    const int qb = (gridDim.x - 1) - blockIdx.x;     // heavy tiles first
    const int h  = blockIdx.y, b = blockIdx.z;
    const int q_base = qb * AQT;
    const int ntile = qb + 1;

    const size_t hb = (((size_t)(b * Hq + h)) * Sq) * HDq;
    const __half* kvsrc[2] = {gkh + hb, gvh + hb};

    auto load_q = [&]() {
        #pragma unroll
        for (int it = 0; it < 4; it++) {
            int i = tid + it * 128;
            int row = i >> 3, ch = i & 7;
            cp_async16(sbase + sw_off(row, ch),
                       gqh + hb + (size_t)(q_base + row) * HDq + ch * 8);
        }
    };
    auto load_kv = [&](int t, int bi) {
        const int k0 = t * AKT;
        const uint32_t sb = sbase + 8192 + (uint32_t)bi * KVSTG;
        #pragma unroll
        for (int it = 0; it < 8; it++) {
            int i = tid + it * 128;              // 1024 chunks (2 arr x 64r x 8ch)
            int arr = i >> 9, rem = i & 511;
            int row = rem >> 3, ch = rem & 7;
            cp_async16(sb + arr * 8192 + sw_off(row, ch),
                       kvsrc[arr] + (size_t)(k0 + row) * HDq + ch * 8);
        }
    };

    float m0 = -1e30f, m1 = -1e30f, l0 = 0.f, l1 = 0.f;
    float o[8][4];
    #pragma unroll
    for (int j = 0; j < 8; j++)
        #pragma unroll
        for (int e = 0; e < 4; e++) o[j][e] = 0.f;

    uint32_t qfh[4][4];
    const int wq = q_base + wid * 16;
    const int qg0 = wq + (lane >> 2);

    auto compute_tile = [&](int t) {
        const int k0 = t * AKT;
        if (k0 > wq + 15) return;
        const uint32_t BUF = sbase + 8192 + (uint32_t)(t & 3) * KVSTG;
        const uint32_t KH = BUF, VH = BUF + 8192;

        float s[8][4];
        #pragma unroll
        for (int nt = 0; nt < 8; nt++)
            #pragma unroll
            for (int e = 0; e < 4; e++) s[nt][e] = 0.f;

        #pragma unroll
        for (int kh4 = 0; kh4 < 4; kh4++) {
            #pragma unroll
            for (int s4 = 0; s4 < 4; s4++) {
                int row = 16 * kh4 + (g >> 1) * 8 + lr;
                int ch  = 2 * s4 + (g & 1);
                uint32_t kf[4];
                ldmx4(KH + sw_off(row, ch), kf);
                mma16816(s[2*kh4],   qfh[s4], kf[0], kf[1]);
                mma16816(s[2*kh4+1], qfh[s4], kf[2], kf[3]);
            }
        }

        if (k0 + AKT - 1 > wq) {
            #pragma unroll
            for (int nt = 0; nt < 8; nt++) {
                int kg = k0 + nt * 8 + (lane & 3) * 2;
                if (kg     > qg0)     s[nt][0] = -1e30f;
                if (kg + 1 > qg0)     s[nt][1] = -1e30f;
                if (kg     > qg0 + 8) s[nt][2] = -1e30f;
                if (kg + 1 > qg0 + 8) s[nt][3] = -1e30f;
            }
        }

        float t0 = -1e30f, t1 = -1e30f;
        #pragma unroll
        for (int nt = 0; nt < 8; nt++) {
            t0 = fmaxf(t0, fmaxf(s[nt][0], s[nt][1]));
            t1 = fmaxf(t1, fmaxf(s[nt][2], s[nt][3]));
        }
        t0 = fmaxf(t0, __shfl_xor_sync(0xffffffffu, t0, 1));
        t0 = fmaxf(t0, __shfl_xor_sync(0xffffffffu, t0, 2));
        t1 = fmaxf(t1, __shfl_xor_sync(0xffffffffu, t1, 1));
        t1 = fmaxf(t1, __shfl_xor_sync(0xffffffffu, t1, 2));
        float mn0 = fmaxf(m0, t0), mn1 = fmaxf(m1, t1);
        float c0 = exp2f(m0 - mn0), c1 = exp2f(m1 - mn1);
        m0 = mn0; m1 = mn1;
        l0 *= c0; l1 *= c1;
        #pragma unroll
        for (int j = 0; j < 8; j++) {
            o[j][0] *= c0; o[j][1] *= c0; o[j][2] *= c1; o[j][3] *= c1;
        }
        #pragma unroll
        for (int nt = 0; nt < 8; nt++) {
            s[nt][0] = exp2f(s[nt][0] - mn0);
            s[nt][1] = exp2f(s[nt][1] - mn0);
            s[nt][2] = exp2f(s[nt][2] - mn1);
            s[nt][3] = exp2f(s[nt][3] - mn1);
            l0 += s[nt][0] + s[nt][1];
            l1 += s[nt][2] + s[nt][3];
        }

        #pragma unroll
        for (int kp = 0; kp < 4; kp++) {
            uint32_t aph[4];
            aph[0] = pack_h(s[2*kp][0],   s[2*kp][1]);
            aph[1] = pack_h(s[2*kp][2],   s[2*kp][3]);
            aph[2] = pack_h(s[2*kp+1][0], s[2*kp+1][1]);
            aph[3] = pack_h(s[2*kp+1][2], s[2*kp+1][3]);
            #pragma unroll
            for (int j2 = 0; j2 < 4; j2++) {
                int row = kp * 16 + (g & 1) * 8 + lr;
                int ch  = 2 * j2 + (g >> 1);
                uint32_t vf[4];
                ldmx4t(VH + sw_off(row, ch), vf);
                mma16816(o[2*j2],   aph, vf[0], vf[1]);
                mma16816(o[2*j2+1], aph, vf[2], vf[3]);
            }
        }
    };

    load_q(); load_kv(0, 0); cp_commit();
    if (ntile > 1) load_kv(1, 1);
    cp_commit();
    cp_wait<0>();
    __syncthreads();

    #pragma unroll
    for (int s4 = 0; s4 < 4; s4++) {
        int row = wid * 16 + (g & 1) * 8 + lr;
        int ch  = 2 * s4 + (g >> 1);
        ldmx4(QH + sw_off(row, ch), qfh[s4]);
    }

    for (int t = 0; t < ntile; t += 2) {
        if (t) { cp_wait<0>(); __syncthreads(); }
        if (t + 2 < ntile) { load_kv(t + 2, (t + 2) & 3); cp_commit(); }
        if (t + 3 < ntile) { load_kv(t + 3, (t + 3) & 3); cp_commit(); }
        compute_tile(t);
        if (t + 1 < ntile) compute_tile(t + 1);
    }

    // ---- normalize + write fp16 hi [b,s,D] (out-proj A operand) ----
    float ls0 = l0 + __shfl_xor_sync(0xffffffffu, l0, 1);
    ls0 += __shfl_xor_sync(0xffffffffu, ls0, 2);
    float ls1 = l1 + __shfl_xor_sync(0xffffffffu, l1, 1);
    ls1 += __shfl_xor_sync(0xffffffffu, ls1, 2);
    const float inv0 = 1.f / ls0, inv1 = 1.f / ls1;

    const size_t base0 = ((size_t)b * Sq + qg0) * Dq + h * HDq;
    const size_t base1 = ((size_t)b * Sq + qg0 + 8) * Dq + h * HDq;
    #pragma unroll
    for (int j = 0; j < 8; j++) {
        int cc = j * 8 + (lane & 3) * 2;
        *(uint32_t*)(outh + base0 + cc) = pack_h(o[j][0] * inv0, o[j][1] * inv0);
        *(uint32_t*)(outh + base1 + cc) = pack_h(o[j][2] * inv1, o[j][3] * inv1);
    }
}

// ---------------------------------------------------------------------------
// Launch
// ---------------------------------------------------------------------------
extern "C" void kernel_launch(void* const* d_in, const int* in_sizes, int n_in,
                              void* d_out, int out_size)
{
    const float* x    = (const float*)d_in[0];
    const float* cosp = (const float*)d_in[1];
    const float* sinp = (const float*)d_in[2];
    // d_in[3] = mask: causal -1e9 — handled analytically, never read.
    const float* Wqkv = (const float*)d_in[4];
    const float* Wout = (const float*)d_in[5];
    float* out = (float*)d_out;

    __half *p_xh, *p_w1h, *p_w2h, *p_ah, *p_qh, *p_kh, *p_vh;
    cudaGetSymbolAddress((void**)&p_xh,  g_xh);
    cudaGetSymbolAddress((void**)&p_w1h, g_w1h);
    cudaGetSymbolAddress((void**)&p_w2h, g_w2h);
    cudaGetSymbolAddress((void**)&p_ah,  g_ah);
    cudaGetSymbolAddress((void**)&p_qh,  g_qh);
    cudaGetSymbolAddress((void**)&p_kh,  g_kh);
    cudaGetSymbolAddress((void**)&p_vh,  g_vh);

    cudaFuncSetAttribute(gemm_qkv_rope, cudaFuncAttributeMaxDynamicSharedMemorySize,
                         GEMM1P_SMEM);
    cudaFuncSetAttribute(gemm_mma_1p, cudaFuncAttributeMaxDynamicSharedMemorySize,
                         GEMM1P_SMEM);
    cudaFuncSetAttribute(attn_mma, cudaFuncAttributeMaxDynamicSharedMemorySize,
                         ATT_SMEM);

    // 0) Conversions: x and weights -> fp16 hi-only
    {
        int n4 = Mrows * Kdim / 4;
        convert_half_kernel<<<(n4 + 255) / 256, 256>>>(x, p_xh, n4);
        dim3 blk(32, 8);
        transpose_half_kernel<<<dim3(3 * Dq / 32, Kdim / 32), blk>>>(Wqkv, p_w1h, Kdim, 3 * Dq);
        transpose_half_kernel<<<dim3(Dq / 32, Kdim / 32), blk>>>(Wout, p_w2h, Kdim, Dq);
    }
    // 1) QKV projection + fused RoPE/transpose (mma.sync fp16, 1-product)
    {
        dim3 grid(3 * Dq / 128, Mrows / 128);
        gemm_qkv_rope<<<grid, 256, GEMM1P_SMEM>>>(p_xh, p_w1h, cosp, sinp,
                                                  p_qh, p_kh, p_vh);
    }
    // 2) Tensor-core causal flash attention (3 CTAs/SM)
    {
        dim3 grid(Sq / AQT, Hq, Bq);
        attn_mma<<<grid, 128, ATT_SMEM>>>(p_qh, p_kh, p_vh, p_ah);
    }
    // 3) Output projection (mma.sync fp16, 1-product)
    {
        dim3 grid(Dq / 128, Mrows / 128);
        gemm_mma_1p<<<grid, 256, GEMM1P_SMEM>>>(p_ah, p_w2h, out, Dq);
    }
}